// round 3
// baseline (speedup 1.0000x reference)
#include <cuda_runtime.h>
#include <cstdint>

#define BB 16
#define LL 256
#define DD 768
#define HH 12
#define HDIM 64
#define NLAYER 4
#define FFD 3072
#define MM (BB*LL)   /* 4096 */
#define CC 2

// ---------------- scratch (device globals; no allocations allowed) ----------
__device__ float g_h[MM*DD];        // hidden state
__device__ float g_q[MM*DD];
__device__ float g_k[MM*DD];
__device__ float g_v[MM*DD];
__device__ float g_attout[MM*DD];
__device__ float g_proj[MM*DD];
__device__ float g_ff[MM*FFD];
__device__ float g_att[(size_t)BB*HH*LL*LL];  // scores then probs, in place

// ---------------- embedding + sinusoidal pos emb ----------------------------
__global__ void embed_kernel(const int* __restrict__ word_ids,
                             const float* __restrict__ word_emb) {
    int row = blockIdx.x;            // b*L + l
    int l   = row % LL;
    int wid = word_ids[row];
    const float* we = word_emb + (size_t)wid * DD;
    float* out = g_h + (size_t)row * DD;
#pragma unroll
    for (int t = 0; t < 3; t++) {
        int d  = threadIdx.x + t * 256;
        int m  = d >> 1;
        float div = __expf(-9.210340371976184f * (float)(2 * m) / (float)DD);
        float ang = (float)l * div;
        float pe  = (d & 1) ? cosf(ang) : sinf(ang);
        out[d] = we[d] + pe;
    }
}

// ---------------- tiled SGEMM: C[M,N] = A[M,K] @ W[K,N] + bias (opt ReLU) ---
template<bool RELU>
__global__ void gemm_bias_kernel(const float* __restrict__ A,
                                 const float* __restrict__ W,
                                 const float* __restrict__ bias,
                                 float* __restrict__ C,
                                 int K, int N) {
    __shared__ float Ast[16][68];   // A tile, transposed: Ast[k][row]
    __shared__ float Bs [16][68];   // B tile: Bs[k][col]
    int tid = threadIdx.x;
    int tx = tid & 15, ty = tid >> 4;
    int rowBase = blockIdx.y * 64;
    int colBase = blockIdx.x * 64;
    float acc[4][4] = {};

    for (int k0 = 0; k0 < K; k0 += 16) {
#pragma unroll
        for (int t = 0; t < 4; t++) {
            int idx = tid + t * 256;
            int r  = idx >> 4, c  = idx & 15;
            Ast[c][r] = A[(size_t)(rowBase + r) * K + k0 + c];
            int r2 = idx >> 6, c2 = idx & 63;
            Bs[r2][c2] = W[(size_t)(k0 + r2) * N + colBase + c2];
        }
        __syncthreads();
#pragma unroll
        for (int kk = 0; kk < 16; kk++) {
            float4 av = *(const float4*)&Ast[kk][ty * 4];
            float4 bv = *(const float4*)&Bs[kk][tx * 4];
            float a_[4] = {av.x, av.y, av.z, av.w};
            float b_[4] = {bv.x, bv.y, bv.z, bv.w};
#pragma unroll
            for (int i = 0; i < 4; i++)
#pragma unroll
                for (int j = 0; j < 4; j++)
                    acc[i][j] += a_[i] * b_[j];
        }
        __syncthreads();
    }
#pragma unroll
    for (int i = 0; i < 4; i++) {
        int r = rowBase + ty * 4 + i;
#pragma unroll
        for (int j = 0; j < 4; j++) {
            int c = colBase + tx * 4 + j;
            float v = acc[i][j] + bias[c];
            if (RELU) v = fmaxf(v, 0.f);
            C[(size_t)r * N + c] = v;
        }
    }
}

// ---------------- scores = qk + q*edge_emb, mask, softmax (fused) -----------
__global__ void scores_softmax_kernel(const float* __restrict__ q,
                                      const float* __restrict__ kmat,
                                      const float* __restrict__ edge_emb,
                                      const int* __restrict__ edge_types,
                                      const int* __restrict__ adj) {
    int i = blockIdx.x, hh = blockIdx.y, b = blockIdx.z;
    int j = threadIdx.x;                 // 256 threads, one per key j
    __shared__ float qs[HDIM];
    __shared__ float red[256];

    if (j < HDIM) qs[j] = q[(size_t)(b * LL + i) * DD + hh * HDIM + j];
    __syncthreads();

    const float4* kp = (const float4*)&kmat[(size_t)(b * LL + j) * DD + hh * HDIM];
    float s = 0.f;
#pragma unroll
    for (int d4 = 0; d4 < 16; d4++) {
        float4 kv = kp[d4];
        s += qs[d4*4+0]*kv.x + qs[d4*4+1]*kv.y + qs[d4*4+2]*kv.z + qs[d4*4+3]*kv.w;
    }
    size_t eidx = (size_t)(b * LL + i) * LL + j;
    int et = edge_types[eidx];
    const float4* ep = (const float4*)&edge_emb[et * HDIM];
    float s2 = 0.f;
#pragma unroll
    for (int d4 = 0; d4 < 16; d4++) {
        float4 ev = ep[d4];
        s2 += qs[d4*4+0]*ev.x + qs[d4*4+1]*ev.y + qs[d4*4+2]*ev.z + qs[d4*4+3]*ev.w;
    }
    // adj is a widened bool: nonzero bit-pattern == true for both int32 and
    // float32 representations.
    float val = (adj[eidx] != 0) ? (s + s2) * 0.125f : -1e9f;

    // max reduce
    red[j] = val; __syncthreads();
    for (int st = 128; st > 0; st >>= 1) {
        if (j < st) red[j] = fmaxf(red[j], red[j + st]);
        __syncthreads();
    }
    float mx = red[0];
    __syncthreads();
    float e = __expf(val - mx);
    red[j] = e; __syncthreads();
    for (int st = 128; st > 0; st >>= 1) {
        if (j < st) red[j] += red[j + st];
        __syncthreads();
    }
    float inv = 1.f / red[0];
    g_att[(((size_t)b * HH + hh) * LL + i) * LL + j] = e * inv;
}

// ---------------- out[b,i,h,:] = sum_j att[b,h,i,j] * v[b,j,h,:] ------------
__global__ void attv_kernel(const float* __restrict__ vmat) {
    int i = blockIdx.x, hh = blockIdx.y, b = blockIdx.z;
    int tid = threadIdx.x;   // 64 threads, one per head-dim d
    __shared__ float as_[LL];
    const float* arow = &g_att[(((size_t)b * HH + hh) * LL + i) * LL];
#pragma unroll
    for (int t = 0; t < 4; t++) as_[tid + t * 64] = arow[tid + t * 64];
    __syncthreads();
    float s = 0.f;
#pragma unroll 4
    for (int j = 0; j < LL; j++)
        s += as_[j] * vmat[(size_t)(b * LL + j) * DD + hh * HDIM + tid];
    g_attout[(size_t)(b * LL + i) * DD + hh * HDIM + tid] = s;
}

// ---------------- h = LayerNorm(h + proj) -----------------------------------
__global__ void resln_kernel(const float* __restrict__ proj,
                             const float* __restrict__ gam,
                             const float* __restrict__ bet) {
    int row = blockIdx.x;
    int tid = threadIdx.x;
    __shared__ float rsum[256], rsq[256];
    float x[3];
    float s = 0.f, ss = 0.f;
#pragma unroll
    for (int t = 0; t < 3; t++) {
        int d = tid + t * 256;
        float v = g_h[(size_t)row * DD + d] + proj[(size_t)row * DD + d];
        x[t] = v; s += v; ss += v * v;
    }
    rsum[tid] = s; rsq[tid] = ss; __syncthreads();
    for (int st = 128; st > 0; st >>= 1) {
        if (tid < st) { rsum[tid] += rsum[tid + st]; rsq[tid] += rsq[tid + st]; }
        __syncthreads();
    }
    float mean = rsum[0] * (1.f / 768.f);
    float var  = rsq[0] * (1.f / 768.f) - mean * mean;
    float inv  = rsqrtf(var + 1e-5f);
#pragma unroll
    for (int t = 0; t < 3; t++) {
        int d = tid + t * 256;
        g_h[(size_t)row * DD + d] = (x[t] - mean) * inv * gam[d] + bet[d];
    }
}

// ---------------- logits[b,c] = h[b,0,:] @ cls_W[:,c] + cls_b[c] ------------
__global__ void classify_kernel(const float* __restrict__ clsW,
                                const float* __restrict__ clsb,
                                float* __restrict__ out) {
    int b = blockIdx.x, c = blockIdx.y;
    int tid = threadIdx.x;
    __shared__ float red[256];
    const float* hrow = &g_h[(size_t)(b * LL) * DD];
    float s = 0.f;
    for (int d = tid; d < DD; d += 256) s += hrow[d] * clsW[d * CC + c];
    red[tid] = s; __syncthreads();
    for (int st = 128; st > 0; st >>= 1) {
        if (tid < st) red[tid] += red[tid + st];
        __syncthreads();
    }
    if (tid == 0) out[b * CC + c] = red[0] + clsb[c];
}

// ---------------- driver ----------------------------------------------------
extern "C" void kernel_launch(void* const* d_in, const int* in_sizes, int n_in,
                              void* d_out, int out_size) {
    const int*   word_ids   = (const int*)d_in[0];
    const int*   adj        = (const int*)d_in[1];   // widened bool
    const int*   edge_types = (const int*)d_in[2];
    const float* word_emb   = (const float*)d_in[3];
    const float* edge_emb   = (const float*)d_in[4];
    const float* Wq  = (const float*)d_in[5];
    const float* bq  = (const float*)d_in[6];
    const float* Wk  = (const float*)d_in[7];
    const float* bk  = (const float*)d_in[8];
    const float* Wv  = (const float*)d_in[9];
    const float* bv  = (const float*)d_in[10];
    const float* Wo  = (const float*)d_in[11];
    const float* bo  = (const float*)d_in[12];
    const float* ln1g = (const float*)d_in[13];
    const float* ln1b = (const float*)d_in[14];
    const float* W1  = (const float*)d_in[15];
    const float* b1  = (const float*)d_in[16];
    const float* W2  = (const float*)d_in[17];
    const float* b2  = (const float*)d_in[18];
    const float* ln2g = (const float*)d_in[19];
    const float* ln2b = (const float*)d_in[20];
    const float* clsW = (const float*)d_in[21];
    const float* clsb = (const float*)d_in[22];
    float* out = (float*)d_out;

    float *hptr, *qptr, *kptr, *vptr, *aoptr, *pptr, *fptr;
    cudaGetSymbolAddress((void**)&hptr,  g_h);
    cudaGetSymbolAddress((void**)&qptr,  g_q);
    cudaGetSymbolAddress((void**)&kptr,  g_k);
    cudaGetSymbolAddress((void**)&vptr,  g_v);
    cudaGetSymbolAddress((void**)&aoptr, g_attout);
    cudaGetSymbolAddress((void**)&pptr,  g_proj);
    cudaGetSymbolAddress((void**)&fptr,  g_ff);

    dim3 gD(DD / 64, MM / 64);    // N=768 gemms
    dim3 gF(FFD / 64, MM / 64);   // N=3072 gemm

    embed_kernel<<<MM, 256>>>(word_ids, word_emb);

    for (int l = 0; l < NLAYER; l++) {
        const size_t wdd = (size_t)l * DD * DD;
        gemm_bias_kernel<false><<<gD, 256>>>(hptr, Wq + wdd, bq + l * DD, qptr, DD, DD);
        gemm_bias_kernel<false><<<gD, 256>>>(hptr, Wk + wdd, bk + l * DD, kptr, DD, DD);
        gemm_bias_kernel<false><<<gD, 256>>>(hptr, Wv + wdd, bv + l * DD, vptr, DD, DD);

        scores_softmax_kernel<<<dim3(LL, HH, BB), 256>>>(qptr, kptr, edge_emb, edge_types, adj);
        attv_kernel<<<dim3(LL, HH, BB), 64>>>(vptr);

        gemm_bias_kernel<false><<<gD, 256>>>(aoptr, Wo + wdd, bo + l * DD, pptr, DD, DD);
        resln_kernel<<<MM, 256>>>(pptr, ln1g + l * DD, ln1b + l * DD);

        gemm_bias_kernel<true ><<<gF, 256>>>(hptr, W1 + (size_t)l * DD * FFD, b1 + l * FFD, fptr, DD, FFD);
        gemm_bias_kernel<false><<<gD, 256>>>(fptr, W2 + (size_t)l * FFD * DD, b2 + l * DD, pptr, FFD, DD);
        resln_kernel<<<MM, 256>>>(pptr, ln2g + l * DD, ln2b + l * DD);
    }

    classify_kernel<<<dim3(BB, CC), 256>>>(clsW, clsb, out);
}

// round 5
// speedup vs baseline: 1.6498x; 1.6498x over previous
#include <cuda_runtime.h>
#include <cstdint>

#define BB 16
#define LL 256
#define DD 768
#define HH 12
#define HDIM 64
#define NLAYER 4
#define FFD 3072
#define MM (BB*LL)   /* 4096 */
#define CC 2
#define EE 50

// ---------------- scratch (device globals; no allocations allowed) ----------
__device__ float g_h[MM*DD];
__device__ float g_q[MM*DD];
__device__ float g_k[MM*DD];
__device__ float g_v[MM*DD];
__device__ float g_attout[MM*DD];
__device__ float g_proj[MM*DD];
__device__ float g_ff[MM*FFD];

// ---------------- embedding + sinusoidal pos emb ----------------------------
__global__ void embed_kernel(const int* __restrict__ word_ids,
                             const float* __restrict__ word_emb) {
    int row = blockIdx.x;
    int l   = row % LL;
    int wid = word_ids[row];
    const float* we = word_emb + (size_t)wid * DD;
    float* out = g_h + (size_t)row * DD;
#pragma unroll
    for (int t = 0; t < 3; t++) {
        int d  = threadIdx.x + t * 256;
        int m  = d >> 1;
        float div = __expf(-9.210340371976184f * (float)(2 * m) / (float)DD);
        float ang = (float)l * div;
        float pe  = (d & 1) ? cosf(ang) : sinf(ang);
        out[d] = we[d] + pe;
    }
}

// ---------------- 128x128x8 double-buffered SGEMM + bias (opt ReLU) ---------
template<bool RELU>
__global__ __launch_bounds__(256, 2)
void gemm128_kernel(const float* __restrict__ A,
                    const float* __restrict__ W,
                    const float* __restrict__ bias,
                    float* __restrict__ C,
                    int K, int N) {
    __shared__ float As[2][8][128];   // transposed: As[k][m]
    __shared__ float Bs[2][8][128];   // Bs[k][n]

    int tid = threadIdx.x;
    int tx = tid & 15, ty = tid >> 4;           // 16 x 16 thread grid
    int rowBase = blockIdx.y * 128;
    int colBase = blockIdx.x * 128;

    int arow  = tid >> 1;                       // 0..127
    int acol4 = (tid & 1) * 4;                  // 0 or 4
    int brow  = tid >> 5;                       // 0..7
    int bcol4 = (tid & 31) * 4;                 // 0..124

    const float* Aptr = A + (size_t)(rowBase + arow) * K + acol4;
    const float* Bptr = W + (size_t)brow * N + colBase + bcol4;

    // first tile
    float4 av = *(const float4*)Aptr;
    float4 bv = *(const float4*)Bptr;
    As[0][acol4+0][arow] = av.x;
    As[0][acol4+1][arow] = av.y;
    As[0][acol4+2][arow] = av.z;
    As[0][acol4+3][arow] = av.w;
    *(float4*)&Bs[0][brow][bcol4] = bv;
    __syncthreads();

    float acc[8][8] = {};
    int nk = K >> 3;
    int cur = 0;

    for (int kt = 0; kt < nk; kt++) {
        float4 an, bn;
        bool more = (kt + 1 < nk);
        if (more) {
            an = *(const float4*)(Aptr + (kt + 1) * 8);
            bn = *(const float4*)(Bptr + (size_t)(kt + 1) * 8 * N);
        }
#pragma unroll
        for (int kk = 0; kk < 8; kk++) {
            float a[8], b[8];
            *(float4*)&a[0] = *(const float4*)&As[cur][kk][ty * 8];
            *(float4*)&a[4] = *(const float4*)&As[cur][kk][ty * 8 + 4];
            *(float4*)&b[0] = *(const float4*)&Bs[cur][kk][tx * 8];
            *(float4*)&b[4] = *(const float4*)&Bs[cur][kk][tx * 8 + 4];
#pragma unroll
            for (int i = 0; i < 8; i++)
#pragma unroll
                for (int j = 0; j < 8; j++)
                    acc[i][j] += a[i] * b[j];
        }
        if (more) {
            int nxt = cur ^ 1;
            As[nxt][acol4+0][arow] = an.x;
            As[nxt][acol4+1][arow] = an.y;
            As[nxt][acol4+2][arow] = an.z;
            As[nxt][acol4+3][arow] = an.w;
            *(float4*)&Bs[nxt][brow][bcol4] = bn;
            cur = nxt;
        }
        __syncthreads();
    }

    float bcol[8];
#pragma unroll
    for (int j = 0; j < 8; j++) bcol[j] = bias[colBase + tx * 8 + j];

#pragma unroll
    for (int i = 0; i < 8; i++) {
        size_t r = rowBase + ty * 8 + i;
        float o[8];
#pragma unroll
        for (int j = 0; j < 8; j++) {
            float v = acc[i][j] + bcol[j];
            if (RELU) v = fmaxf(v, 0.f);
            o[j] = v;
        }
        *(float4*)&C[r * N + colBase + tx * 8]     = *(float4*)&o[0];
        *(float4*)&C[r * N + colBase + tx * 8 + 4] = *(float4*)&o[4];
    }
}

// ---------------- fused attention: scores + edge + mask + softmax + att@V ---
#define ISPLIT 2
#define IBLK 4
#define KST 68     /* K/V smem row stride (floats); mult of 4 -> 16B rows */
#define EST 68     /* edge-table stride; mult of 4 keeps later regions aligned */
// smem floats: Ks 256*68 + Vs 256*68 + Et 50*68 + qv 256 + qe 4*52 + pb 4*256
//              + red 32 + mxs 8 + avs 256  = 40000 floats (160000 B)
#define ATT_SMEM_FLOATS (256*KST*2 + EE*EST + 256 + IBLK*52 + IBLK*256 + 32 + 8 + 256)

__global__ __launch_bounds__(256)
void attn_fused_kernel(const float* __restrict__ q,
                       const float* __restrict__ k,
                       const float* __restrict__ v,
                       const float* __restrict__ edge_emb,
                       const int* __restrict__ edge_types,
                       const int* __restrict__ adj,
                       float* __restrict__ outp) {
    extern __shared__ float sm[];
    float* Ks  = sm;                       // [256][KST]
    float* Vs  = Ks + 256 * KST;           // [256][KST]
    float* Et  = Vs + 256 * KST;           // [50][EST]
    float* qv  = Et + EE * EST;            // [IBLK][64]   (offset mult of 4)
    float* qe  = qv + IBLK * 64;           // [IBLK][52]
    float* pb  = qe + IBLK * 52;           // [IBLK][256]  (offset mult of 4)
    float* red = pb + IBLK * 256;          // [IBLK*8]
    float* mxs = red + 32;                 // [8]: max[4], inv-denom[4]
    float* avs = mxs + 8;                  // [256]

    int h = blockIdx.x, b = blockIdx.y;
    int tid  = threadIdx.x;
    int lane = tid & 31, wrp = tid >> 5;

    // ---- load K, V tiles (coalesced float4 gmem reads) ----
    const float* kbase = k + (size_t)(b * LL) * DD + h * HDIM;
    const float* vbase = v + (size_t)(b * LL) * DD + h * HDIM;
#pragma unroll
    for (int t = 0; t < 16; t++) {
        int idx = tid + t * 256;           // over 256*16 float4 slots
        int j = idx >> 4, d4 = (idx & 15) * 4;
        float4 kv = *(const float4*)(kbase + (size_t)j * DD + d4);
        float4 vv = *(const float4*)(vbase + (size_t)j * DD + d4);
        Ks[j*KST + d4+0] = kv.x; Ks[j*KST + d4+1] = kv.y;
        Ks[j*KST + d4+2] = kv.z; Ks[j*KST + d4+3] = kv.w;
        Vs[j*KST + d4+0] = vv.x; Vs[j*KST + d4+1] = vv.y;
        Vs[j*KST + d4+2] = vv.z; Vs[j*KST + d4+3] = vv.w;
    }
    for (int idx = tid; idx < EE * 16; idx += 256) {
        int e = idx >> 4, d4 = (idx & 15) * 4;
        float4 ev = *(const float4*)(edge_emb + e * HDIM + d4);
        Et[e*EST + d4+0] = ev.x; Et[e*EST + d4+1] = ev.y;
        Et[e*EST + d4+2] = ev.z; Et[e*EST + d4+3] = ev.w;
    }
    __syncthreads();

    int i0 = blockIdx.z * (LL / ISPLIT);
    for (int qd = 0; qd < (LL / ISPLIT) / IBLK; qd++) {
        int ibase = i0 + qd * IBLK;

        // load q rows for this quad
        {
            int iq = tid >> 6, d = tid & 63;
            qv[iq * 64 + d] = q[(size_t)(b * LL + ibase + iq) * DD + h * HDIM + d];
        }
        __syncthreads();

        // qe[iq][e] = q_iq . edge_emb[e]
        if (tid < IBLK * EE) {
            int iq = tid / EE, e = tid % EE;
            float s = 0.f;
            const float* qr = qv + iq * 64;
            const float* er = Et + e * EST;
#pragma unroll 8
            for (int d = 0; d < 64; d++) s += qr[d] * er[d];
            qe[iq * 52 + e] = s;
        }
        __syncthreads();

        // qk scores: thread = key index j
        int j = tid;
        float sarr[IBLK] = {};
        {
            const float4* Kr = (const float4*)(Ks + j * KST);
            const float4* Q0 = (const float4*)(qv);
            const float4* Q1 = (const float4*)(qv + 64);
            const float4* Q2 = (const float4*)(qv + 128);
            const float4* Q3 = (const float4*)(qv + 192);
#pragma unroll
            for (int d4 = 0; d4 < 16; d4++) {
                float4 kv = Kr[d4];
                float4 a;
                a = Q0[d4]; sarr[0] += a.x*kv.x + a.y*kv.y + a.z*kv.z + a.w*kv.w;
                a = Q1[d4]; sarr[1] += a.x*kv.x + a.y*kv.y + a.z*kv.z + a.w*kv.w;
                a = Q2[d4]; sarr[2] += a.x*kv.x + a.y*kv.y + a.z*kv.z + a.w*kv.w;
                a = Q3[d4]; sarr[3] += a.x*kv.x + a.y*kv.y + a.z*kv.z + a.w*kv.w;
            }
        }
        // edge lookup + mask + scale
#pragma unroll
        for (int iq = 0; iq < IBLK; iq++) {
            size_t eidx = (size_t)(b * LL + ibase + iq) * LL + j;
            int et = edge_types[eidx];
            sarr[iq] = (adj[eidx] != 0)
                     ? (sarr[iq] + qe[iq * 52 + et]) * 0.125f
                     : -1e9f;
        }
        // softmax: block max per iq
#pragma unroll
        for (int iq = 0; iq < IBLK; iq++) {
            float m = sarr[iq];
#pragma unroll
            for (int o = 16; o > 0; o >>= 1)
                m = fmaxf(m, __shfl_xor_sync(0xffffffffu, m, o));
            if (lane == 0) red[iq * 8 + wrp] = m;
        }
        __syncthreads();
        if (tid < IBLK) {
            float m = red[tid * 8];
#pragma unroll
            for (int w = 1; w < 8; w++) m = fmaxf(m, red[tid * 8 + w]);
            mxs[tid] = m;
        }
        __syncthreads();
        float ev[IBLK];
#pragma unroll
        for (int iq = 0; iq < IBLK; iq++) {
            ev[iq] = __expf(sarr[iq] - mxs[iq]);
            pb[iq * 256 + j] = ev[iq];
        }
#pragma unroll
        for (int iq = 0; iq < IBLK; iq++) {
            float s = ev[iq];
#pragma unroll
            for (int o = 16; o > 0; o >>= 1)
                s += __shfl_xor_sync(0xffffffffu, s, o);
            if (lane == 0) red[iq * 8 + wrp] = s;
        }
        __syncthreads();
        if (tid < IBLK) {
            float s = 0.f;
#pragma unroll
            for (int w = 0; w < 8; w++) s += red[tid * 8 + w];
            mxs[IBLK + tid] = 1.f / s;
        }
        __syncthreads();

        // att @ V : threads (part, d); 4 partial sums reduced via smem
        int d = tid & 63, part = tid >> 6;
#pragma unroll
        for (int iq = 0; iq < IBLK; iq++) {
            float acc = 0.f;
            const float4* pr = (const float4*)(pb + iq * 256 + part * 64);
            const float* vr = Vs + (size_t)(part * 64) * KST + d;
#pragma unroll 4
            for (int j4 = 0; j4 < 16; j4++) {
                float4 p4 = pr[j4];
                acc += p4.x * vr[(j4*4+0)*KST];
                acc += p4.y * vr[(j4*4+1)*KST];
                acc += p4.z * vr[(j4*4+2)*KST];
                acc += p4.w * vr[(j4*4+3)*KST];
            }
            avs[tid] = acc;
            __syncthreads();
            if (part == 0) {
                float o = (avs[d] + avs[64+d] + avs[128+d] + avs[192+d])
                          * mxs[IBLK + iq];
                outp[(size_t)(b * LL + ibase + iq) * DD + h * HDIM + d] = o;
            }
            __syncthreads();
        }
    }
}

// ---------------- h = LayerNorm(h + proj) -----------------------------------
__global__ void resln_kernel(const float* __restrict__ proj,
                             const float* __restrict__ gam,
                             const float* __restrict__ bet) {
    int row = blockIdx.x;
    int tid = threadIdx.x;
    __shared__ float rsum[256], rsq[256];
    float x[3];
    float s = 0.f, ss = 0.f;
#pragma unroll
    for (int t = 0; t < 3; t++) {
        int d = tid + t * 256;
        float v = g_h[(size_t)row * DD + d] + proj[(size_t)row * DD + d];
        x[t] = v; s += v; ss += v * v;
    }
    rsum[tid] = s; rsq[tid] = ss; __syncthreads();
    for (int st = 128; st > 0; st >>= 1) {
        if (tid < st) { rsum[tid] += rsum[tid + st]; rsq[tid] += rsq[tid + st]; }
        __syncthreads();
    }
    float mean = rsum[0] * (1.f / 768.f);
    float var  = rsq[0] * (1.f / 768.f) - mean * mean;
    float inv  = rsqrtf(var + 1e-5f);
#pragma unroll
    for (int t = 0; t < 3; t++) {
        int d = tid + t * 256;
        g_h[(size_t)row * DD + d] = (x[t] - mean) * inv * gam[d] + bet[d];
    }
}

// ---------------- logits ----------------------------------------------------
__global__ void classify_kernel(const float* __restrict__ clsW,
                                const float* __restrict__ clsb,
                                float* __restrict__ out) {
    int b = blockIdx.x, c = blockIdx.y;
    int tid = threadIdx.x;
    __shared__ float red[256];
    const float* hrow = &g_h[(size_t)(b * LL) * DD];
    float s = 0.f;
    for (int d = tid; d < DD; d += 256) s += hrow[d] * clsW[d * CC + c];
    red[tid] = s; __syncthreads();
    for (int st = 128; st > 0; st >>= 1) {
        if (tid < st) red[tid] += red[tid + st];
        __syncthreads();
    }
    if (tid == 0) out[b * CC + c] = red[0] + clsb[c];
}

// ---------------- driver ----------------------------------------------------
extern "C" void kernel_launch(void* const* d_in, const int* in_sizes, int n_in,
                              void* d_out, int out_size) {
    const int*   word_ids   = (const int*)d_in[0];
    const int*   adj        = (const int*)d_in[1];   // widened bool
    const int*   edge_types = (const int*)d_in[2];
    const float* word_emb   = (const float*)d_in[3];
    const float* edge_emb   = (const float*)d_in[4];
    const float* Wq  = (const float*)d_in[5];
    const float* bq  = (const float*)d_in[6];
    const float* Wk  = (const float*)d_in[7];
    const float* bk  = (const float*)d_in[8];
    const float* Wv  = (const float*)d_in[9];
    const float* bv  = (const float*)d_in[10];
    const float* Wo  = (const float*)d_in[11];
    const float* bo  = (const float*)d_in[12];
    const float* ln1g = (const float*)d_in[13];
    const float* ln1b = (const float*)d_in[14];
    const float* W1  = (const float*)d_in[15];
    const float* b1  = (const float*)d_in[16];
    const float* W2  = (const float*)d_in[17];
    const float* b2  = (const float*)d_in[18];
    const float* ln2g = (const float*)d_in[19];
    const float* ln2b = (const float*)d_in[20];
    const float* clsW = (const float*)d_in[21];
    const float* clsb = (const float*)d_in[22];
    float* out = (float*)d_out;

    float *hptr, *qptr, *kptr, *vptr, *aoptr, *pptr, *fptr;
    cudaGetSymbolAddress((void**)&hptr,  g_h);
    cudaGetSymbolAddress((void**)&qptr,  g_q);
    cudaGetSymbolAddress((void**)&kptr,  g_k);
    cudaGetSymbolAddress((void**)&vptr,  g_v);
    cudaGetSymbolAddress((void**)&aoptr, g_attout);
    cudaGetSymbolAddress((void**)&pptr,  g_proj);
    cudaGetSymbolAddress((void**)&fptr,  g_ff);

    const int attSmem = ATT_SMEM_FLOATS * 4;
    cudaFuncSetAttribute(attn_fused_kernel,
                         cudaFuncAttributeMaxDynamicSharedMemorySize, attSmem);

    dim3 gD(DD / 128, MM / 128);     // (6, 32)
    dim3 gF(FFD / 128, MM / 128);    // (24, 32)

    embed_kernel<<<MM, 256>>>(word_ids, word_emb);

    for (int l = 0; l < NLAYER; l++) {
        const size_t wdd = (size_t)l * DD * DD;
        gemm128_kernel<false><<<gD, 256>>>(hptr, Wq + wdd, bq + l * DD, qptr, DD, DD);
        gemm128_kernel<false><<<gD, 256>>>(hptr, Wk + wdd, bk + l * DD, kptr, DD, DD);
        gemm128_kernel<false><<<gD, 256>>>(hptr, Wv + wdd, bv + l * DD, vptr, DD, DD);

        attn_fused_kernel<<<dim3(HH, BB, ISPLIT), 256, attSmem>>>(
            qptr, kptr, vptr, edge_emb, edge_types, adj, aoptr);

        gemm128_kernel<false><<<gD, 256>>>(aoptr, Wo + wdd, bo + l * DD, pptr, DD, DD);
        resln_kernel<<<MM, 256>>>(pptr, ln1g + l * DD, ln1b + l * DD);

        gemm128_kernel<true ><<<gF, 256>>>(hptr, W1 + (size_t)l * DD * FFD, b1 + l * FFD, fptr, DD, FFD);
        gemm128_kernel<false><<<gD, 256>>>(fptr, W2 + (size_t)l * FFD * DD, b2 + l * DD, pptr, FFD, DD);
        resln_kernel<<<MM, 256>>>(pptr, ln2g + l * DD, ln2b + l * DD);
    }

    classify_kernel<<<dim3(BB, CC), 256>>>(clsW, clsb, out);
}

// round 6
// speedup vs baseline: 1.7598x; 1.0667x over previous
#include <cuda_runtime.h>
#include <cuda_bf16.h>
#include <mma.h>
#include <cstdint>

using namespace nvcuda;

#define BB 16
#define LL 256
#define DD 768
#define HH 12
#define HDIM 64
#define NLAYER 4
#define FFD 3072
#define MM (BB*LL)   /* 4096 */
#define CC 2
#define EE 50
#define K3D (3*DD)    /* 2304 */
#define K3F (3*FFD)   /* 9216 */

// ---------------- scratch (device globals; no allocations allowed) ----------
__device__ float g_h[MM*DD];
__device__ float g_q[MM*DD];
__device__ float g_k[MM*DD];
__device__ float g_v[MM*DD];
__device__ float g_proj[MM*DD];
__device__ __nv_bfloat16 g_h3[(size_t)MM*K3D];     // packed [Ahi|Ahi|Alo] of h
__device__ __nv_bfloat16 g_ao3[(size_t)MM*K3D];    // packed attention output
__device__ __nv_bfloat16 g_ff3[(size_t)MM*K3F];    // packed FFN intermediate
__device__ __nv_bfloat16 g_wp [(size_t)NLAYER*4*K3D*DD];   // Wq,Wk,Wv,Wo packed
__device__ __nv_bfloat16 g_w1p[(size_t)NLAYER*K3D*FFD];    // W1 packed
__device__ __nv_bfloat16 g_w2p[(size_t)NLAYER*K3F*DD];     // W2 packed

__device__ __forceinline__ void split_bf16(float v, __nv_bfloat16& hi, __nv_bfloat16& lo) {
    hi = __float2bfloat16_rn(v);
    lo = __float2bfloat16_rn(v - __bfloat162float(hi));
}

// ---------------- weight packing: W[K][N] -> W3[[Whi];[Wlo];[Whi]] ----------
__global__ void pack_w_kernel(const float* __restrict__ W,
                              __nv_bfloat16* __restrict__ W3,
                              int K, int N) {
    int idx = blockIdx.x * 256 + threadIdx.x;
    if (idx >= K * N) return;
    float w = W[idx];
    __nv_bfloat16 hi, lo; split_bf16(w, hi, lo);
    W3[idx] = hi;
    W3[(size_t)K * N + idx] = lo;
    W3[(size_t)2 * K * N + idx] = hi;
}

// ---------------- embedding + sinusoidal pos emb (+ packed h3) --------------
__global__ void embed_kernel(const int* __restrict__ word_ids,
                             const float* __restrict__ word_emb) {
    int row = blockIdx.x;
    int l   = row % LL;
    int wid = word_ids[row];
    const float* we = word_emb + (size_t)wid * DD;
    float* out = g_h + (size_t)row * DD;
    __nv_bfloat16* p3 = g_h3 + (size_t)row * K3D;
#pragma unroll
    for (int t = 0; t < 3; t++) {
        int d  = threadIdx.x + t * 256;
        int m  = d >> 1;
        float div = __expf(-9.210340371976184f * (float)(2 * m) / (float)DD);
        float ang = (float)l * div;
        float pe  = (d & 1) ? cosf(ang) : sinf(ang);
        float v = we[d] + pe;
        out[d] = v;
        __nv_bfloat16 hi, lo; split_bf16(v, hi, lo);
        p3[d] = hi; p3[DD + d] = hi; p3[2*DD + d] = lo;
    }
}

// ---------------- WMMA bf16 GEMM: C = A3[M][K3] @ B3[K3][N] + bias ----------
// MODE 0: fp32 output Cf.  MODE 1: packed bf16 output Cp ([hi|hi|lo] over N).
#define AST 40    /* A smem stride (bf16) */
#define BST 136   /* B smem stride (bf16) */
#define CST 132   /* C staging stride (fp32) */
#define GEMM_SMEM (128*CST*4)   /* 67584 B; tiles (18944 B) alias the front */

template<bool RELU, int MODE>
__global__ __launch_bounds__(256)
void gemm_bf16_kernel(const __nv_bfloat16* __restrict__ A,
                      const __nv_bfloat16* __restrict__ B,
                      const float* __restrict__ bias,
                      float* __restrict__ Cf,
                      __nv_bfloat16* __restrict__ Cp,
                      int K3, int N) {
    extern __shared__ char smbuf[];
    __nv_bfloat16* As = (__nv_bfloat16*)smbuf;       // [128][AST]
    __nv_bfloat16* Bs = As + 128 * AST;              // [32][BST]
    float* Cs = (float*)smbuf;                       // [128][CST] (aliases)

    int tid = threadIdx.x;
    int wid = tid >> 5;
    int warpM = wid & 3;     // 32-row slab
    int warpN = wid >> 2;    // 64-col slab
    int rowBase = blockIdx.y * 128;
    int colBase = blockIdx.x * 128;

    wmma::fragment<wmma::accumulator, 16,16,16, float> acc[2][4];
#pragma unroll
    for (int i = 0; i < 2; i++)
#pragma unroll
        for (int j = 0; j < 4; j++) wmma::fill_fragment(acc[i][j], 0.f);

    int ar = tid >> 1;             // 0..127
    int ac = (tid & 1) * 16;       // 0/16
    int br = tid >> 3;             // 0..31
    int bc = (tid & 7) * 16;       // 0..112

    const __nv_bfloat16* Ag = A + (size_t)(rowBase + ar) * K3 + ac;
    const __nv_bfloat16* Bg = B + (size_t)br * N + colBase + bc;

    for (int kt = 0; kt < K3; kt += 32) {
        const uint4* ap = (const uint4*)(Ag + kt);
        uint4 a0 = ap[0], a1 = ap[1];
        const uint4* bp = (const uint4*)(Bg + (size_t)kt * N);
        uint4 b0 = bp[0], b1 = bp[1];
        *(uint4*)&As[ar*AST + ac]     = a0;
        *(uint4*)&As[ar*AST + ac + 8] = a1;
        *(uint4*)&Bs[br*BST + bc]     = b0;
        *(uint4*)&Bs[br*BST + bc + 8] = b1;
        __syncthreads();
#pragma unroll
        for (int ks = 0; ks < 32; ks += 16) {
            wmma::fragment<wmma::matrix_a, 16,16,16, __nv_bfloat16, wmma::row_major> af[2];
            wmma::fragment<wmma::matrix_b, 16,16,16, __nv_bfloat16, wmma::row_major> bfr[4];
#pragma unroll
            for (int i = 0; i < 2; i++)
                wmma::load_matrix_sync(af[i], &As[(warpM*32 + i*16)*AST + ks], AST);
#pragma unroll
            for (int j = 0; j < 4; j++)
                wmma::load_matrix_sync(bfr[j], &Bs[ks*BST + warpN*64 + j*16], BST);
#pragma unroll
            for (int i = 0; i < 2; i++)
#pragma unroll
                for (int j = 0; j < 4; j++)
                    wmma::mma_sync(acc[i][j], af[i], bfr[j], acc[i][j]);
        }
        __syncthreads();
    }

    // stage to smem
#pragma unroll
    for (int i = 0; i < 2; i++)
#pragma unroll
        for (int j = 0; j < 4; j++)
            wmma::store_matrix_sync(&Cs[(warpM*32 + i*16)*CST + warpN*64 + j*16],
                                    acc[i][j], CST, wmma::mem_row_major);
    __syncthreads();

    int r  = tid >> 1;
    int c0 = (tid & 1) * 64;
    if (MODE == 0) {
#pragma unroll
        for (int c4 = 0; c4 < 64; c4 += 4) {
            int c = c0 + c4;
            float4 v = *(float4*)&Cs[r*CST + c];
            v.x += bias[colBase + c + 0];
            v.y += bias[colBase + c + 1];
            v.z += bias[colBase + c + 2];
            v.w += bias[colBase + c + 3];
            if (RELU) {
                v.x = fmaxf(v.x, 0.f); v.y = fmaxf(v.y, 0.f);
                v.z = fmaxf(v.z, 0.f); v.w = fmaxf(v.w, 0.f);
            }
            *(float4*)&Cf[(size_t)(rowBase + r) * N + colBase + c] = v;
        }
    } else {
        size_t rowb = (size_t)(rowBase + r) * (3 * (size_t)N);
#pragma unroll
        for (int c2 = 0; c2 < 64; c2 += 2) {
            int c = c0 + c2;
            float v0 = Cs[r*CST + c]     + bias[colBase + c];
            float v1 = Cs[r*CST + c + 1] + bias[colBase + c + 1];
            if (RELU) { v0 = fmaxf(v0, 0.f); v1 = fmaxf(v1, 0.f); }
            __nv_bfloat16 h0, l0, h1, l1;
            split_bf16(v0, h0, l0); split_bf16(v1, h1, l1);
            __nv_bfloat162 hh; hh.x = h0; hh.y = h1;
            __nv_bfloat162 llv; llv.x = l0; llv.y = l1;
            *(__nv_bfloat162*)&Cp[rowb + colBase + c]             = hh;
            *(__nv_bfloat162*)&Cp[rowb + N + colBase + c]         = hh;
            *(__nv_bfloat162*)&Cp[rowb + 2*(size_t)N + colBase + c] = llv;
        }
    }
}

// ---------------- fused attention (unchanged math; packed bf16 output) ------
#define ISPLIT 2
#define IBLK 4
#define KST 68
#define EST 68
#define ATT_SMEM_FLOATS (256*KST*2 + EE*EST + 256 + IBLK*52 + IBLK*256 + 32 + 8 + 256)

__global__ __launch_bounds__(256)
void attn_fused_kernel(const float* __restrict__ q,
                       const float* __restrict__ k,
                       const float* __restrict__ v,
                       const float* __restrict__ edge_emb,
                       const int* __restrict__ edge_types,
                       const int* __restrict__ adj,
                       __nv_bfloat16* __restrict__ outp3) {
    extern __shared__ float sm[];
    float* Ks  = sm;
    float* Vs  = Ks + 256 * KST;
    float* Et  = Vs + 256 * KST;
    float* qv  = Et + EE * EST;
    float* qe  = qv + IBLK * 64;
    float* pb  = qe + IBLK * 52;
    float* red = pb + IBLK * 256;
    float* mxs = red + 32;
    float* avs = mxs + 8;

    int h = blockIdx.x, b = blockIdx.y;
    int tid  = threadIdx.x;
    int lane = tid & 31, wrp = tid >> 5;

    const float* kbase = k + (size_t)(b * LL) * DD + h * HDIM;
    const float* vbase = v + (size_t)(b * LL) * DD + h * HDIM;
#pragma unroll
    for (int t = 0; t < 16; t++) {
        int idx = tid + t * 256;
        int j = idx >> 4, d4 = (idx & 15) * 4;
        float4 kv = *(const float4*)(kbase + (size_t)j * DD + d4);
        float4 vv = *(const float4*)(vbase + (size_t)j * DD + d4);
        Ks[j*KST + d4+0] = kv.x; Ks[j*KST + d4+1] = kv.y;
        Ks[j*KST + d4+2] = kv.z; Ks[j*KST + d4+3] = kv.w;
        Vs[j*KST + d4+0] = vv.x; Vs[j*KST + d4+1] = vv.y;
        Vs[j*KST + d4+2] = vv.z; Vs[j*KST + d4+3] = vv.w;
    }
    for (int idx = tid; idx < EE * 16; idx += 256) {
        int e = idx >> 4, d4 = (idx & 15) * 4;
        float4 ev = *(const float4*)(edge_emb + e * HDIM + d4);
        Et[e*EST + d4+0] = ev.x; Et[e*EST + d4+1] = ev.y;
        Et[e*EST + d4+2] = ev.z; Et[e*EST + d4+3] = ev.w;
    }
    __syncthreads();

    int i0 = blockIdx.z * (LL / ISPLIT);
    for (int qd = 0; qd < (LL / ISPLIT) / IBLK; qd++) {
        int ibase = i0 + qd * IBLK;
        {
            int iq = tid >> 6, d = tid & 63;
            qv[iq * 64 + d] = q[(size_t)(b * LL + ibase + iq) * DD + h * HDIM + d];
        }
        __syncthreads();

        if (tid < IBLK * EE) {
            int iq = tid / EE, e = tid % EE;
            float s = 0.f;
            const float* qr = qv + iq * 64;
            const float* er = Et + e * EST;
#pragma unroll 8
            for (int d = 0; d < 64; d++) s += qr[d] * er[d];
            qe[iq * 52 + e] = s;
        }
        __syncthreads();

        int j = tid;
        float sarr[IBLK] = {};
        {
            const float4* Kr = (const float4*)(Ks + j * KST);
            const float4* Q0 = (const float4*)(qv);
            const float4* Q1 = (const float4*)(qv + 64);
            const float4* Q2 = (const float4*)(qv + 128);
            const float4* Q3 = (const float4*)(qv + 192);
#pragma unroll
            for (int d4 = 0; d4 < 16; d4++) {
                float4 kv = Kr[d4];
                float4 a;
                a = Q0[d4]; sarr[0] += a.x*kv.x + a.y*kv.y + a.z*kv.z + a.w*kv.w;
                a = Q1[d4]; sarr[1] += a.x*kv.x + a.y*kv.y + a.z*kv.z + a.w*kv.w;
                a = Q2[d4]; sarr[2] += a.x*kv.x + a.y*kv.y + a.z*kv.z + a.w*kv.w;
                a = Q3[d4]; sarr[3] += a.x*kv.x + a.y*kv.y + a.z*kv.z + a.w*kv.w;
            }
        }
#pragma unroll
        for (int iq = 0; iq < IBLK; iq++) {
            size_t eidx = (size_t)(b * LL + ibase + iq) * LL + j;
            int et = edge_types[eidx];
            sarr[iq] = (adj[eidx] != 0)
                     ? (sarr[iq] + qe[iq * 52 + et]) * 0.125f
                     : -1e9f;
        }
#pragma unroll
        for (int iq = 0; iq < IBLK; iq++) {
            float m = sarr[iq];
#pragma unroll
            for (int o = 16; o > 0; o >>= 1)
                m = fmaxf(m, __shfl_xor_sync(0xffffffffu, m, o));
            if (lane == 0) red[iq * 8 + wrp] = m;
        }
        __syncthreads();
        if (tid < IBLK) {
            float m = red[tid * 8];
#pragma unroll
            for (int w = 1; w < 8; w++) m = fmaxf(m, red[tid * 8 + w]);
            mxs[tid] = m;
        }
        __syncthreads();
        float ev[IBLK];
#pragma unroll
        for (int iq = 0; iq < IBLK; iq++) {
            ev[iq] = __expf(sarr[iq] - mxs[iq]);
            pb[iq * 256 + j] = ev[iq];
        }
#pragma unroll
        for (int iq = 0; iq < IBLK; iq++) {
            float s = ev[iq];
#pragma unroll
            for (int o = 16; o > 0; o >>= 1)
                s += __shfl_xor_sync(0xffffffffu, s, o);
            if (lane == 0) red[iq * 8 + wrp] = s;
        }
        __syncthreads();
        if (tid < IBLK) {
            float s = 0.f;
#pragma unroll
            for (int w = 0; w < 8; w++) s += red[tid * 8 + w];
            mxs[IBLK + tid] = 1.f / s;
        }
        __syncthreads();

        int d = tid & 63, part = tid >> 6;
#pragma unroll
        for (int iq = 0; iq < IBLK; iq++) {
            float acc = 0.f;
            const float4* pr = (const float4*)(pb + iq * 256 + part * 64);
            const float* vr = Vs + (size_t)(part * 64) * KST + d;
#pragma unroll 4
            for (int j4 = 0; j4 < 16; j4++) {
                float4 p4 = pr[j4];
                acc += p4.x * vr[(j4*4+0)*KST];
                acc += p4.y * vr[(j4*4+1)*KST];
                acc += p4.z * vr[(j4*4+2)*KST];
                acc += p4.w * vr[(j4*4+3)*KST];
            }
            avs[tid] = acc;
            __syncthreads();
            if (part == 0) {
                float o = (avs[d] + avs[64+d] + avs[128+d] + avs[192+d])
                          * mxs[IBLK + iq];
                size_t base = (size_t)(b * LL + ibase + iq) * K3D + h * HDIM + d;
                __nv_bfloat16 hi, lo; split_bf16(o, hi, lo);
                outp3[base] = hi; outp3[base + DD] = hi; outp3[base + 2*DD] = lo;
            }
            __syncthreads();
        }
    }
}

// ---------------- h = LayerNorm(h + proj); also writes packed h3 ------------
__global__ void resln_kernel(const float* __restrict__ proj,
                             const float* __restrict__ gam,
                             const float* __restrict__ bet) {
    int row = blockIdx.x;
    int tid = threadIdx.x;
    __shared__ float rsum[256], rsq[256];
    float x[3];
    float s = 0.f, ss = 0.f;
#pragma unroll
    for (int t = 0; t < 3; t++) {
        int d = tid + t * 256;
        float v = g_h[(size_t)row * DD + d] + proj[(size_t)row * DD + d];
        x[t] = v; s += v; ss += v * v;
    }
    rsum[tid] = s; rsq[tid] = ss; __syncthreads();
    for (int st = 128; st > 0; st >>= 1) {
        if (tid < st) { rsum[tid] += rsum[tid + st]; rsq[tid] += rsq[tid + st]; }
        __syncthreads();
    }
    float mean = rsum[0] * (1.f / 768.f);
    float var  = rsq[0] * (1.f / 768.f) - mean * mean;
    float inv  = rsqrtf(var + 1e-5f);
    __nv_bfloat16* p3 = g_h3 + (size_t)row * K3D;
#pragma unroll
    for (int t = 0; t < 3; t++) {
        int d = tid + t * 256;
        float y = (x[t] - mean) * inv * gam[d] + bet[d];
        g_h[(size_t)row * DD + d] = y;
        __nv_bfloat16 hi, lo; split_bf16(y, hi, lo);
        p3[d] = hi; p3[DD + d] = hi; p3[2*DD + d] = lo;
    }
}

// ---------------- logits ----------------------------------------------------
__global__ void classify_kernel(const float* __restrict__ clsW,
                                const float* __restrict__ clsb,
                                float* __restrict__ out) {
    int b = blockIdx.x, c = blockIdx.y;
    int tid = threadIdx.x;
    __shared__ float red[256];
    const float* hrow = &g_h[(size_t)(b * LL) * DD];
    float s = 0.f;
    for (int d = tid; d < DD; d += 256) s += hrow[d] * clsW[d * CC + c];
    red[tid] = s; __syncthreads();
    for (int st = 128; st > 0; st >>= 1) {
        if (tid < st) red[tid] += red[tid + st];
        __syncthreads();
    }
    if (tid == 0) out[b * CC + c] = red[0] + clsb[c];
}

// ---------------- driver ----------------------------------------------------
extern "C" void kernel_launch(void* const* d_in, const int* in_sizes, int n_in,
                              void* d_out, int out_size) {
    const int*   word_ids   = (const int*)d_in[0];
    const int*   adj        = (const int*)d_in[1];   // widened bool
    const int*   edge_types = (const int*)d_in[2];
    const float* word_emb   = (const float*)d_in[3];
    const float* edge_emb   = (const float*)d_in[4];
    const float* Wq  = (const float*)d_in[5];
    const float* bq  = (const float*)d_in[6];
    const float* Wk  = (const float*)d_in[7];
    const float* bk  = (const float*)d_in[8];
    const float* Wv  = (const float*)d_in[9];
    const float* bv  = (const float*)d_in[10];
    const float* Wo  = (const float*)d_in[11];
    const float* bo  = (const float*)d_in[12];
    const float* ln1g = (const float*)d_in[13];
    const float* ln1b = (const float*)d_in[14];
    const float* W1  = (const float*)d_in[15];
    const float* b1  = (const float*)d_in[16];
    const float* W2  = (const float*)d_in[17];
    const float* b2  = (const float*)d_in[18];
    const float* ln2g = (const float*)d_in[19];
    const float* ln2b = (const float*)d_in[20];
    const float* clsW = (const float*)d_in[21];
    const float* clsb = (const float*)d_in[22];
    float* out = (float*)d_out;

    float *qptr, *kptr, *vptr, *pptr;
    __nv_bfloat16 *h3ptr, *ao3ptr, *ff3ptr, *wpptr, *w1pptr, *w2pptr;
    cudaGetSymbolAddress((void**)&qptr,  g_q);
    cudaGetSymbolAddress((void**)&kptr,  g_k);
    cudaGetSymbolAddress((void**)&vptr,  g_v);
    cudaGetSymbolAddress((void**)&pptr,  g_proj);
    cudaGetSymbolAddress((void**)&h3ptr, g_h3);
    cudaGetSymbolAddress((void**)&ao3ptr, g_ao3);
    cudaGetSymbolAddress((void**)&ff3ptr, g_ff3);
    cudaGetSymbolAddress((void**)&wpptr,  g_wp);
    cudaGetSymbolAddress((void**)&w1pptr, g_w1p);
    cudaGetSymbolAddress((void**)&w2pptr, g_w2p);

    cudaFuncSetAttribute(gemm_bf16_kernel<false,0>,
                         cudaFuncAttributeMaxDynamicSharedMemorySize, GEMM_SMEM);
    cudaFuncSetAttribute(gemm_bf16_kernel<true,1>,
                         cudaFuncAttributeMaxDynamicSharedMemorySize, GEMM_SMEM);
    const int attSmem = ATT_SMEM_FLOATS * 4;
    cudaFuncSetAttribute(attn_fused_kernel,
                         cudaFuncAttributeMaxDynamicSharedMemorySize, attSmem);

    // ---- pack all weights (runs in-graph; pure bandwidth) ----
    const int nDD = DD * DD, nDF = DD * FFD;
    for (int l = 0; l < NLAYER; l++) {
        size_t wsl = (size_t)l * DD * DD;
        pack_w_kernel<<<(nDD+255)/256, 256>>>(Wq + wsl, wpptr + (size_t)(l*4+0)*K3D*DD, DD, DD);
        pack_w_kernel<<<(nDD+255)/256, 256>>>(Wk + wsl, wpptr + (size_t)(l*4+1)*K3D*DD, DD, DD);
        pack_w_kernel<<<(nDD+255)/256, 256>>>(Wv + wsl, wpptr + (size_t)(l*4+2)*K3D*DD, DD, DD);
        pack_w_kernel<<<(nDD+255)/256, 256>>>(Wo + wsl, wpptr + (size_t)(l*4+3)*K3D*DD, DD, DD);
        pack_w_kernel<<<(nDF+255)/256, 256>>>(W1 + (size_t)l*nDF, w1pptr + (size_t)l*K3D*FFD, DD, FFD);
        pack_w_kernel<<<(nDF+255)/256, 256>>>(W2 + (size_t)l*nDF, w2pptr + (size_t)l*K3F*DD, FFD, DD);
    }

    dim3 gD(DD / 128, MM / 128);     // (6, 32)
    dim3 gF(FFD / 128, MM / 128);    // (24, 32)

    embed_kernel<<<MM, 256>>>(word_ids, word_emb);

    for (int l = 0; l < NLAYER; l++) {
        const __nv_bfloat16* wq3 = wpptr + (size_t)(l*4+0)*K3D*DD;
        const __nv_bfloat16* wk3 = wpptr + (size_t)(l*4+1)*K3D*DD;
        const __nv_bfloat16* wv3 = wpptr + (size_t)(l*4+2)*K3D*DD;
        const __nv_bfloat16* wo3 = wpptr + (size_t)(l*4+3)*K3D*DD;

        gemm_bf16_kernel<false,0><<<gD, 256, GEMM_SMEM>>>(h3ptr, wq3, bq + l*DD, qptr, nullptr, K3D, DD);
        gemm_bf16_kernel<false,0><<<gD, 256, GEMM_SMEM>>>(h3ptr, wk3, bk + l*DD, kptr, nullptr, K3D, DD);
        gemm_bf16_kernel<false,0><<<gD, 256, GEMM_SMEM>>>(h3ptr, wv3, bv + l*DD, vptr, nullptr, K3D, DD);

        attn_fused_kernel<<<dim3(HH, BB, ISPLIT), 256, attSmem>>>(
            qptr, kptr, vptr, edge_emb, edge_types, adj, ao3ptr);

        gemm_bf16_kernel<false,0><<<gD, 256, GEMM_SMEM>>>(ao3ptr, wo3, bo + l*DD, pptr, nullptr, K3D, DD);
        resln_kernel<<<MM, 256>>>(pptr, ln1g + l*DD, ln1b + l*DD);

        gemm_bf16_kernel<true,1><<<gF, 256, GEMM_SMEM>>>(h3ptr, w1pptr + (size_t)l*K3D*FFD,
                                                         b1 + l*FFD, nullptr, ff3ptr, K3D, FFD);
        gemm_bf16_kernel<false,0><<<gD, 256, GEMM_SMEM>>>(ff3ptr, w2pptr + (size_t)l*K3F*DD,
                                                          b2 + l*DD, pptr, nullptr, K3F, DD);
        resln_kernel<<<MM, 256>>>(pptr, ln2g + l*DD, ln2b + l*DD);
    }

    classify_kernel<<<dim3(BB, CC), 256>>>(clsW, clsb, out);
}

// round 8
// speedup vs baseline: 2.2028x; 1.2518x over previous
#include <cuda_runtime.h>
#include <cuda_bf16.h>
#include <mma.h>
#include <cstdint>

using namespace nvcuda;

#define BB 16
#define LL 256
#define DD 768
#define HH 12
#define HDIM 64
#define NLAYER 4
#define FFD 3072
#define MM (BB*LL)   /* 4096 */
#define CC 2
#define EE 50
#define K3D (3*DD)    /* 2304 */
#define K3F (3*FFD)   /* 9216 */

// ---------------- scratch (device globals; no allocations allowed) ----------
__device__ float g_h[MM*DD];
__device__ float g_q[MM*DD];
__device__ float g_k[MM*DD];
__device__ float g_v[MM*DD];
__device__ float g_proj[MM*DD];
__device__ __nv_bfloat16 g_h3[(size_t)MM*K3D];     // packed [Ahi|Ahi|Alo] rows
__device__ __nv_bfloat16 g_ao3[(size_t)MM*K3D];
__device__ __nv_bfloat16 g_ff3[(size_t)MM*K3F];
__device__ __nv_bfloat16 g_wp [(size_t)NLAYER*4*DD*K3D];   // transposed [N][3K]
__device__ __nv_bfloat16 g_w1p[(size_t)NLAYER*FFD*K3D];
__device__ __nv_bfloat16 g_w2p[(size_t)NLAYER*DD*K3F];

__device__ __forceinline__ void split_bf16(float v, __nv_bfloat16& hi, __nv_bfloat16& lo) {
    hi = __float2bfloat16_rn(v);
    lo = __float2bfloat16_rn(v - __bfloat162float(hi));
}
__device__ __forceinline__ uint32_t smem_u32(const void* p) {
    uint32_t a;
    asm("{ .reg .u64 t; cvta.to.shared.u64 t, %1; cvt.u32.u64 %0, t; }" : "=r"(a) : "l"(p));
    return a;
}
#define CP_ASYNC16(dst, src) \
    asm volatile("cp.async.cg.shared.global [%0], [%1], 16;" :: "r"(dst), "l"(src))
#define CP_COMMIT() asm volatile("cp.async.commit_group;" ::: "memory")
#define CP_WAIT2()  asm volatile("cp.async.wait_group 2;" ::: "memory")
#define CP_WAIT0()  asm volatile("cp.async.wait_group 0;" ::: "memory")

// ---------------- weight pack + transpose: W[K][N] -> Wt3[N][3K] ------------
// k3 order [Whi | Wlo | Whi] matches A3 rows [Ahi | Ahi | Alo].
__global__ void pack_wT_kernel(const float* __restrict__ W,
                               __nv_bfloat16* __restrict__ Wt3,
                               int K, int N) {
    __shared__ float tile[32][33];
    int k0 = blockIdx.x * 32, n0 = blockIdx.y * 32;
    int tx = threadIdx.x, ty = threadIdx.y;   // 32 x 8
#pragma unroll
    for (int j = 0; j < 32; j += 8)
        tile[ty + j][tx] = W[(size_t)(k0 + ty + j) * N + n0 + tx];
    __syncthreads();
#pragma unroll
    for (int j = 0; j < 32; j += 8) {
        float w = tile[tx][ty + j];           // W[k0+tx][n0+ty+j]
        __nv_bfloat16 hi, lo; split_bf16(w, hi, lo);
        size_t base = (size_t)(n0 + ty + j) * (3 * (size_t)K) + k0 + tx;
        Wt3[base] = hi; Wt3[base + K] = lo; Wt3[base + 2 * K] = hi;
    }
}

// ---------------- embedding + pos emb (+ packed h3) -------------------------
__global__ void embed_kernel(const int* __restrict__ word_ids,
                             const float* __restrict__ word_emb) {
    int row = blockIdx.x;
    int l   = row % LL;
    int wid = word_ids[row];
    const float* we = word_emb + (size_t)wid * DD;
    float* out = g_h + (size_t)row * DD;
    __nv_bfloat16* p3 = g_h3 + (size_t)row * K3D;
#pragma unroll
    for (int t = 0; t < 3; t++) {
        int d  = threadIdx.x + t * 256;
        int m  = d >> 1;
        float div = __expf(-9.210340371976184f * (float)(2 * m) / (float)DD);
        float ang = (float)l * div;
        float pe  = (d & 1) ? cosf(ang) : sinf(ang);
        float v = we[d] + pe;
        out[d] = v;
        __nv_bfloat16 hi, lo; split_bf16(v, hi, lo);
        p3[d] = hi; p3[DD + d] = hi; p3[2*DD + d] = lo;
    }
}

// ---------------- WMMA bf16 GEMM, 4-stage cp.async pipeline -----------------
// C[M,N] = A3[M,K3] @ Wt3[N,K3]^T + bias.  MODE 0: fp32 out; MODE 1: packed.
#define AST 40          /* smem tile stride (bf16 elems): 80B, 16B-multiple */
#define STG_ELEMS (128*AST)      /* 5120 elems = 10240 B per tile per stage */
#define CST 132
#define GEMM_SMEM (8*STG_ELEMS*2)   /* 81920 B >= Cs 128*132*4 = 67584 B */

template<bool RELU, int MODE>
__global__ __launch_bounds__(256)
void gemm_mma_kernel(const __nv_bfloat16* __restrict__ A,
                     const __nv_bfloat16* __restrict__ Bt,
                     const float* __restrict__ bias,
                     float* __restrict__ Cf,
                     __nv_bfloat16* __restrict__ Cp,
                     int K3, int N) {
    extern __shared__ char smraw[];
    __nv_bfloat16* As = (__nv_bfloat16*)smraw;          // [4][128][AST]
    __nv_bfloat16* Bs = As + 4 * STG_ELEMS;             // [4][128][AST]
    float* Cs = (float*)smraw;                           // alias (epilogue)

    int tid = threadIdx.x;
    int wid = tid >> 5;
    int warpM = wid & 1;      // 64-row slab
    int warpN = wid >> 1;     // 32-col slab
    int rowBase = blockIdx.y * 128;
    int colBase = blockIdx.x * 128;

    const __nv_bfloat16* Ag = A  + (size_t)rowBase * K3;
    const __nv_bfloat16* Bg = Bt + (size_t)colBase * K3;
    uint32_t asB = smem_u32(As);
    uint32_t bsB = smem_u32(Bs);

    int r0 = tid >> 2;          // 0..63 base row
    int sg = tid & 3;           // 16B segment (8 bf16)
    int NK = K3 >> 5;           // 32-K chunks

    auto load_stage = [&](int stage, int kb) {
        uint32_t sOff = (uint32_t)stage * (STG_ELEMS * 2);
        size_t gk = (size_t)kb * 32 + sg * 8;
#pragma unroll
        for (int t = 0; t < 2; t++) {
            int row = r0 + t * 64;
            uint32_t so = sOff + (uint32_t)row * (AST * 2) + sg * 16;
            CP_ASYNC16(asB + so, Ag + (size_t)row * K3 + gk);
            CP_ASYNC16(bsB + so, Bg + (size_t)row * K3 + gk);
        }
    };

    wmma::fragment<wmma::accumulator, 16,16,16, float> acc[4][2];
#pragma unroll
    for (int i = 0; i < 4; i++)
#pragma unroll
        for (int j = 0; j < 2; j++) wmma::fill_fragment(acc[i][j], 0.f);

    load_stage(0, 0); CP_COMMIT();
    load_stage(1, 1); CP_COMMIT();
    load_stage(2, 2); CP_COMMIT();

    for (int i = 0; i < NK; i++) {
        CP_WAIT2();
        __syncthreads();
        int st = i & 3;
        const __nv_bfloat16* Ast = As + st * STG_ELEMS;
        const __nv_bfloat16* Bst = Bs + st * STG_ELEMS;
#pragma unroll
        for (int ks = 0; ks < 32; ks += 16) {
            wmma::fragment<wmma::matrix_a, 16,16,16, __nv_bfloat16, wmma::row_major> af[4];
            wmma::fragment<wmma::matrix_b, 16,16,16, __nv_bfloat16, wmma::col_major> bf[2];
#pragma unroll
            for (int m4 = 0; m4 < 4; m4++)
                wmma::load_matrix_sync(af[m4], &Ast[(warpM*64 + m4*16)*AST + ks], AST);
#pragma unroll
            for (int n2 = 0; n2 < 2; n2++)
                wmma::load_matrix_sync(bf[n2], &Bst[(warpN*32 + n2*16)*AST + ks], AST);
#pragma unroll
            for (int m4 = 0; m4 < 4; m4++)
#pragma unroll
                for (int n2 = 0; n2 < 2; n2++)
                    wmma::mma_sync(acc[m4][n2], af[m4], bf[n2], acc[m4][n2]);
        }
        __syncthreads();
        if (i + 3 < NK) load_stage((i + 3) & 3, i + 3);
        CP_COMMIT();
    }
    CP_WAIT0();
    __syncthreads();

    // ---- epilogue: frags -> smem stage -> fused bias/relu -> gmem ----
#pragma unroll
    for (int m4 = 0; m4 < 4; m4++)
#pragma unroll
        for (int n2 = 0; n2 < 2; n2++)
            wmma::store_matrix_sync(&Cs[(warpM*64 + m4*16)*CST + warpN*32 + n2*16],
                                    acc[m4][n2], CST, wmma::mem_row_major);
    __syncthreads();

    int r  = tid >> 1;
    int c0 = (tid & 1) * 64;
    if (MODE == 0) {
#pragma unroll
        for (int c4 = 0; c4 < 64; c4 += 4) {
            int c = c0 + c4;
            float4 v = *(float4*)&Cs[r*CST + c];
            v.x += bias[colBase + c + 0];
            v.y += bias[colBase + c + 1];
            v.z += bias[colBase + c + 2];
            v.w += bias[colBase + c + 3];
            if (RELU) {
                v.x = fmaxf(v.x, 0.f); v.y = fmaxf(v.y, 0.f);
                v.z = fmaxf(v.z, 0.f); v.w = fmaxf(v.w, 0.f);
            }
            *(float4*)&Cf[(size_t)(rowBase + r) * N + colBase + c] = v;
        }
    } else {
        size_t rowb = (size_t)(rowBase + r) * (3 * (size_t)N);
#pragma unroll
        for (int c2 = 0; c2 < 64; c2 += 2) {
            int c = c0 + c2;
            float v0 = Cs[r*CST + c]     + bias[colBase + c];
            float v1 = Cs[r*CST + c + 1] + bias[colBase + c + 1];
            if (RELU) { v0 = fmaxf(v0, 0.f); v1 = fmaxf(v1, 0.f); }
            __nv_bfloat16 h0, l0, h1, l1;
            split_bf16(v0, h0, l0); split_bf16(v1, h1, l1);
            __nv_bfloat162 hh; hh.x = h0; hh.y = h1;
            __nv_bfloat162 llv; llv.x = l0; llv.y = l1;
            *(__nv_bfloat162*)&Cp[rowb + colBase + c]               = hh;
            *(__nv_bfloat162*)&Cp[rowb + N + colBase + c]           = hh;
            *(__nv_bfloat162*)&Cp[rowb + 2*(size_t)N + colBase + c] = llv;
        }
    }
}

// ---------------- fused attention (packed bf16 output) ----------------------
#define ISPLIT 2
#define IBLK 4
#define KST 68
#define EST 68
#define ATT_SMEM_FLOATS (256*KST*2 + EE*EST + 256 + IBLK*52 + IBLK*256 + 32 + 8 + 256)

__global__ __launch_bounds__(256)
void attn_fused_kernel(const float* __restrict__ q,
                       const float* __restrict__ k,
                       const float* __restrict__ v,
                       const float* __restrict__ edge_emb,
                       const int* __restrict__ edge_types,
                       const int* __restrict__ adj,
                       __nv_bfloat16* __restrict__ outp3) {
    extern __shared__ float sm[];
    float* Ks  = sm;
    float* Vs  = Ks + 256 * KST;
    float* Et  = Vs + 256 * KST;
    float* qv  = Et + EE * EST;
    float* qe  = qv + IBLK * 64;
    float* pb  = qe + IBLK * 52;
    float* red = pb + IBLK * 256;
    float* mxs = red + 32;
    float* avs = mxs + 8;

    int h = blockIdx.x, b = blockIdx.y;
    int tid  = threadIdx.x;
    int lane = tid & 31, wrp = tid >> 5;

    const float* kbase = k + (size_t)(b * LL) * DD + h * HDIM;
    const float* vbase = v + (size_t)(b * LL) * DD + h * HDIM;
#pragma unroll
    for (int t = 0; t < 16; t++) {
        int idx = tid + t * 256;
        int j = idx >> 4, d4 = (idx & 15) * 4;
        float4 kv = *(const float4*)(kbase + (size_t)j * DD + d4);
        float4 vv = *(const float4*)(vbase + (size_t)j * DD + d4);
        Ks[j*KST + d4+0] = kv.x; Ks[j*KST + d4+1] = kv.y;
        Ks[j*KST + d4+2] = kv.z; Ks[j*KST + d4+3] = kv.w;
        Vs[j*KST + d4+0] = vv.x; Vs[j*KST + d4+1] = vv.y;
        Vs[j*KST + d4+2] = vv.z; Vs[j*KST + d4+3] = vv.w;
    }
    for (int idx = tid; idx < EE * 16; idx += 256) {
        int e = idx >> 4, d4 = (idx & 15) * 4;
        float4 ev = *(const float4*)(edge_emb + e * HDIM + d4);
        Et[e*EST + d4+0] = ev.x; Et[e*EST + d4+1] = ev.y;
        Et[e*EST + d4+2] = ev.z; Et[e*EST + d4+3] = ev.w;
    }
    __syncthreads();

    int i0 = blockIdx.z * (LL / ISPLIT);
    for (int qd = 0; qd < (LL / ISPLIT) / IBLK; qd++) {
        int ibase = i0 + qd * IBLK;
        {
            int iq = tid >> 6, d = tid & 63;
            qv[iq * 64 + d] = q[(size_t)(b * LL + ibase + iq) * DD + h * HDIM + d];
        }
        __syncthreads();

        if (tid < IBLK * EE) {
            int iq = tid / EE, e = tid % EE;
            float s = 0.f;
            const float* qr = qv + iq * 64;
            const float* er = Et + e * EST;
#pragma unroll 8
            for (int d = 0; d < 64; d++) s += qr[d] * er[d];
            qe[iq * 52 + e] = s;
        }
        __syncthreads();

        int j = tid;
        float sarr[IBLK] = {};
        {
            const float4* Kr = (const float4*)(Ks + j * KST);
            const float4* Q0 = (const float4*)(qv);
            const float4* Q1 = (const float4*)(qv + 64);
            const float4* Q2 = (const float4*)(qv + 128);
            const float4* Q3 = (const float4*)(qv + 192);
#pragma unroll
            for (int d4 = 0; d4 < 16; d4++) {
                float4 kv = Kr[d4];
                float4 a;
                a = Q0[d4]; sarr[0] += a.x*kv.x + a.y*kv.y + a.z*kv.z + a.w*kv.w;
                a = Q1[d4]; sarr[1] += a.x*kv.x + a.y*kv.y + a.z*kv.z + a.w*kv.w;
                a = Q2[d4]; sarr[2] += a.x*kv.x + a.y*kv.y + a.z*kv.z + a.w*kv.w;
                a = Q3[d4]; sarr[3] += a.x*kv.x + a.y*kv.y + a.z*kv.z + a.w*kv.w;
            }
        }
#pragma unroll
        for (int iq = 0; iq < IBLK; iq++) {
            size_t eidx = (size_t)(b * LL + ibase + iq) * LL + j;
            int et = edge_types[eidx];
            sarr[iq] = (adj[eidx] != 0)
                     ? (sarr[iq] + qe[iq * 52 + et]) * 0.125f
                     : -1e9f;
        }
#pragma unroll
        for (int iq = 0; iq < IBLK; iq++) {
            float m = sarr[iq];
#pragma unroll
            for (int o = 16; o > 0; o >>= 1)
                m = fmaxf(m, __shfl_xor_sync(0xffffffffu, m, o));
            if (lane == 0) red[iq * 8 + wrp] = m;
        }
        __syncthreads();
        if (tid < IBLK) {
            float m = red[tid * 8];
#pragma unroll
            for (int w = 1; w < 8; w++) m = fmaxf(m, red[tid * 8 + w]);
            mxs[tid] = m;
        }
        __syncthreads();
        float ev[IBLK];
#pragma unroll
        for (int iq = 0; iq < IBLK; iq++) {
            ev[iq] = __expf(sarr[iq] - mxs[iq]);
            pb[iq * 256 + j] = ev[iq];
        }
#pragma unroll
        for (int iq = 0; iq < IBLK; iq++) {
            float s = ev[iq];
#pragma unroll
            for (int o = 16; o > 0; o >>= 1)
                s += __shfl_xor_sync(0xffffffffu, s, o);
            if (lane == 0) red[iq * 8 + wrp] = s;
        }
        __syncthreads();
        if (tid < IBLK) {
            float s = 0.f;
#pragma unroll
            for (int w = 0; w < 8; w++) s += red[tid * 8 + w];
            mxs[IBLK + tid] = 1.f / s;
        }
        __syncthreads();

        int d = tid & 63, part = tid >> 6;
#pragma unroll
        for (int iq = 0; iq < IBLK; iq++) {
            float acc = 0.f;
            const float4* pr = (const float4*)(pb + iq * 256 + part * 64);
            const float* vr = Vs + (size_t)(part * 64) * KST + d;
#pragma unroll 4
            for (int j4 = 0; j4 < 16; j4++) {
                float4 p4 = pr[j4];
                acc += p4.x * vr[(j4*4+0)*KST];
                acc += p4.y * vr[(j4*4+1)*KST];
                acc += p4.z * vr[(j4*4+2)*KST];
                acc += p4.w * vr[(j4*4+3)*KST];
            }
            avs[tid] = acc;
            __syncthreads();
            if (part == 0) {
                float o = (avs[d] + avs[64+d] + avs[128+d] + avs[192+d])
                          * mxs[IBLK + iq];
                size_t base = (size_t)(b * LL + ibase + iq) * K3D + h * HDIM + d;
                __nv_bfloat16 hi, lo; split_bf16(o, hi, lo);
                outp3[base] = hi; outp3[base + DD] = hi; outp3[base + 2*DD] = lo;
            }
            __syncthreads();
        }
    }
}

// ---------------- h = LayerNorm(h + proj); writes h + packed h3 -------------
__global__ void resln_kernel(const float* __restrict__ proj,
                             const float* __restrict__ gam,
                             const float* __restrict__ bet) {
    int row = blockIdx.x;
    int tid = threadIdx.x;
    __shared__ float rsum[256], rsq[256];
    float x[3];
    float s = 0.f, ss = 0.f;
#pragma unroll
    for (int t = 0; t < 3; t++) {
        int d = tid + t * 256;
        float v = g_h[(size_t)row * DD + d] + proj[(size_t)row * DD + d];
        x[t] = v; s += v; ss += v * v;
    }
    rsum[tid] = s; rsq[tid] = ss; __syncthreads();
    for (int st = 128; st > 0; st >>= 1) {
        if (tid < st) { rsum[tid] += rsum[tid + st]; rsq[tid] += rsq[tid + st]; }
        __syncthreads();
    }
    float mean = rsum[0] * (1.f / 768.f);
    float var  = rsq[0] * (1.f / 768.f) - mean * mean;
    float inv  = rsqrtf(var + 1e-5f);
    __nv_bfloat16* p3 = g_h3 + (size_t)row * K3D;
#pragma unroll
    for (int t = 0; t < 3; t++) {
        int d = tid + t * 256;
        float y = (x[t] - mean) * inv * gam[d] + bet[d];
        g_h[(size_t)row * DD + d] = y;
        __nv_bfloat16 hi, lo; split_bf16(y, hi, lo);
        p3[d] = hi; p3[DD + d] = hi; p3[2*DD + d] = lo;
    }
}

// ---------------- logits ----------------------------------------------------
__global__ void classify_kernel(const float* __restrict__ clsW,
                                const float* __restrict__ clsb,
                                float* __restrict__ out) {
    int b = blockIdx.x, c = blockIdx.y;
    int tid = threadIdx.x;
    __shared__ float red[256];
    const float* hrow = &g_h[(size_t)(b * LL) * DD];
    float s = 0.f;
    for (int d = tid; d < DD; d += 256) s += hrow[d] * clsW[d * CC + c];
    red[tid] = s; __syncthreads();
    for (int st = 128; st > 0; st >>= 1) {
        if (tid < st) red[tid] += red[tid + st];
        __syncthreads();
    }
    if (tid == 0) out[b * CC + c] = red[0] + clsb[c];
}

// ---------------- driver ----------------------------------------------------
extern "C" void kernel_launch(void* const* d_in, const int* in_sizes, int n_in,
                              void* d_out, int out_size) {
    const int*   word_ids   = (const int*)d_in[0];
    const int*   adj        = (const int*)d_in[1];
    const int*   edge_types = (const int*)d_in[2];
    const float* word_emb   = (const float*)d_in[3];
    const float* edge_emb   = (const float*)d_in[4];
    const float* Wq  = (const float*)d_in[5];
    const float* bq  = (const float*)d_in[6];
    const float* Wk  = (const float*)d_in[7];
    const float* bk  = (const float*)d_in[8];
    const float* Wv  = (const float*)d_in[9];
    const float* bv  = (const float*)d_in[10];
    const float* Wo  = (const float*)d_in[11];
    const float* bo  = (const float*)d_in[12];
    const float* ln1g = (const float*)d_in[13];
    const float* ln1b = (const float*)d_in[14];
    const float* W1  = (const float*)d_in[15];
    const float* b1  = (const float*)d_in[16];
    const float* W2  = (const float*)d_in[17];
    const float* b2  = (const float*)d_in[18];
    const float* ln2g = (const float*)d_in[19];
    const float* ln2b = (const float*)d_in[20];
    const float* clsW = (const float*)d_in[21];
    const float* clsb = (const float*)d_in[22];
    float* out = (float*)d_out;

    float *qptr, *kptr, *vptr, *pptr;
    __nv_bfloat16 *h3ptr, *ao3ptr, *ff3ptr, *wpptr, *w1pptr, *w2pptr;
    cudaGetSymbolAddress((void**)&qptr,  g_q);
    cudaGetSymbolAddress((void**)&kptr,  g_k);
    cudaGetSymbolAddress((void**)&vptr,  g_v);
    cudaGetSymbolAddress((void**)&pptr,  g_proj);
    cudaGetSymbolAddress((void**)&h3ptr, g_h3);
    cudaGetSymbolAddress((void**)&ao3ptr, g_ao3);
    cudaGetSymbolAddress((void**)&ff3ptr, g_ff3);
    cudaGetSymbolAddress((void**)&wpptr,  g_wp);
    cudaGetSymbolAddress((void**)&w1pptr, g_w1p);
    cudaGetSymbolAddress((void**)&w2pptr, g_w2p);

    cudaFuncSetAttribute(gemm_mma_kernel<false,0>,
                         cudaFuncAttributeMaxDynamicSharedMemorySize, GEMM_SMEM);
    cudaFuncSetAttribute(gemm_mma_kernel<true,1>,
                         cudaFuncAttributeMaxDynamicSharedMemorySize, GEMM_SMEM);
    const int attSmem = ATT_SMEM_FLOATS * 4;
    cudaFuncSetAttribute(attn_fused_kernel,
                         cudaFuncAttributeMaxDynamicSharedMemorySize, attSmem);

    // ---- pack + transpose all weights ----
    dim3 tb(32, 8);
    for (int l = 0; l < NLAYER; l++) {
        size_t wsl = (size_t)l * DD * DD;
        pack_wT_kernel<<<dim3(DD/32, DD/32), tb>>>(Wq + wsl, wpptr + (size_t)(l*4+0)*DD*K3D, DD, DD);
        pack_wT_kernel<<<dim3(DD/32, DD/32), tb>>>(Wk + wsl, wpptr + (size_t)(l*4+1)*DD*K3D, DD, DD);
        pack_wT_kernel<<<dim3(DD/32, DD/32), tb>>>(Wv + wsl, wpptr + (size_t)(l*4+2)*DD*K3D, DD, DD);
        pack_wT_kernel<<<dim3(DD/32, DD/32), tb>>>(Wo + wsl, wpptr + (size_t)(l*4+3)*DD*K3D, DD, DD);
        pack_wT_kernel<<<dim3(DD/32, FFD/32), tb>>>(W1 + (size_t)l*DD*FFD, w1pptr + (size_t)l*FFD*K3D, DD, FFD);
        pack_wT_kernel<<<dim3(FFD/32, DD/32), tb>>>(W2 + (size_t)l*DD*FFD, w2pptr + (size_t)l*DD*K3F, FFD, DD);
    }

    dim3 gD(DD / 128, MM / 128);     // (6, 32)
    dim3 gF(FFD / 128, MM / 128);    // (24, 32)

    embed_kernel<<<MM, 256>>>(word_ids, word_emb);

    for (int l = 0; l < NLAYER; l++) {
        const __nv_bfloat16* wq3 = wpptr + (size_t)(l*4+0)*DD*K3D;
        const __nv_bfloat16* wk3 = wpptr + (size_t)(l*4+1)*DD*K3D;
        const __nv_bfloat16* wv3 = wpptr + (size_t)(l*4+2)*DD*K3D;
        const __nv_bfloat16* wo3 = wpptr + (size_t)(l*4+3)*DD*K3D;

        gemm_mma_kernel<false,0><<<gD, 256, GEMM_SMEM>>>(h3ptr, wq3, bq + l*DD, qptr, nullptr, K3D, DD);
        gemm_mma_kernel<false,0><<<gD, 256, GEMM_SMEM>>>(h3ptr, wk3, bk + l*DD, kptr, nullptr, K3D, DD);
        gemm_mma_kernel<false,0><<<gD, 256, GEMM_SMEM>>>(h3ptr, wv3, bv + l*DD, vptr, nullptr, K3D, DD);

        attn_fused_kernel<<<dim3(HH, BB, ISPLIT), 256, attSmem>>>(
            qptr, kptr, vptr, edge_emb, edge_types, adj, ao3ptr);

        gemm_mma_kernel<false,0><<<gD, 256, GEMM_SMEM>>>(ao3ptr, wo3, bo + l*DD, pptr, nullptr, K3D, DD);
        resln_kernel<<<MM, 256>>>(pptr, ln1g + l*DD, ln1b + l*DD);

        gemm_mma_kernel<true,1><<<gF, 256, GEMM_SMEM>>>(h3ptr, w1pptr + (size_t)l*FFD*K3D,
                                                        b1 + l*FFD, nullptr, ff3ptr, K3D, FFD);
        gemm_mma_kernel<false,0><<<gD, 256, GEMM_SMEM>>>(ff3ptr, w2pptr + (size_t)l*DD*K3F,
                                                         b2 + l*DD, pptr, nullptr, K3F, DD);
        resln_kernel<<<MM, 256>>>(pptr, ln2g + l*DD, ln2b + l*DD);
    }

    classify_kernel<<<dim3(BB, CC), 256>>>(clsW, clsb, out);
}

// round 9
// speedup vs baseline: 2.4161x; 1.0968x over previous
#include <cuda_runtime.h>
#include <cuda_bf16.h>
#include <mma.h>
#include <cstdint>

using namespace nvcuda;

#define BB 16
#define LL 256
#define DD 768
#define HH 12
#define HDIM 64
#define NLAYER 4
#define FFD 3072
#define MM (BB*LL)   /* 4096 */
#define CC 2
#define EE 50
#define K3D (3*DD)    /* 2304 */
#define K3F (3*FFD)   /* 9216 */
#define NQKV (3*DD)   /* fused QKV output width = 2304 */

// ---------------- scratch (device globals; no allocations allowed) ----------
__device__ float g_h[MM*DD];
__device__ float g_qkv[(size_t)MM*NQKV];           // fused q|k|v fp32
__device__ float g_proj[MM*DD];
__device__ __nv_bfloat16 g_h3[(size_t)MM*K3D];     // packed [Ahi|Ahi|Alo] rows
__device__ __nv_bfloat16 g_ao3[(size_t)MM*K3D];
__device__ __nv_bfloat16 g_ff3[(size_t)MM*K3F];
__device__ __nv_bfloat16 g_wqkv[(size_t)NLAYER*NQKV*K3D];  // [2304][3K] per layer
__device__ __nv_bfloat16 g_wo [(size_t)NLAYER*DD*K3D];
__device__ __nv_bfloat16 g_w1p[(size_t)NLAYER*FFD*K3D];
__device__ __nv_bfloat16 g_w2p[(size_t)NLAYER*DD*K3F];
__device__ float g_bqkv[NLAYER*NQKV];

__device__ __forceinline__ void split_bf16(float v, __nv_bfloat16& hi, __nv_bfloat16& lo) {
    hi = __float2bfloat16_rn(v);
    lo = __float2bfloat16_rn(v - __bfloat162float(hi));
}
__device__ __forceinline__ uint32_t smem_u32(const void* p) {
    uint32_t a;
    asm("{ .reg .u64 t; cvta.to.shared.u64 t, %1; cvt.u32.u64 %0, t; }" : "=r"(a) : "l"(p));
    return a;
}
#define CP_ASYNC16(dst, src) \
    asm volatile("cp.async.cg.shared.global [%0], [%1], 16;" :: "r"(dst), "l"(src))
#define CP_COMMIT() asm volatile("cp.async.commit_group;" ::: "memory")
#define CP_WAIT1()  asm volatile("cp.async.wait_group 1;" ::: "memory")
#define CP_WAIT0()  asm volatile("cp.async.wait_group 0;" ::: "memory")

// ---------------- merged weight pack + transpose ----------------------------
// src W[K][N] -> dst[N][3K] with k3 order [Whi | Wlo | Whi].
__device__ __forceinline__ void packT_tile(const float* __restrict__ W,
                                           __nv_bfloat16* __restrict__ dst,
                                           int K, int N, int k0, int n0,
                                           int tx, int ty) {
    __shared__ float tile[32][33];
#pragma unroll
    for (int j = 0; j < 32; j += 8)
        tile[ty + j][tx] = W[(size_t)(k0 + ty + j) * N + n0 + tx];
    __syncthreads();
#pragma unroll
    for (int j = 0; j < 32; j += 8) {
        float w = tile[tx][ty + j];
        __nv_bfloat16 hi, lo; split_bf16(w, hi, lo);
        size_t base = (size_t)(n0 + ty + j) * (3 * (size_t)K) + k0 + tx;
        dst[base] = hi; dst[base + K] = lo; dst[base + 2 * K] = hi;
    }
}

__global__ void pack_qkvo_kernel(const float* __restrict__ Wq,
                                 const float* __restrict__ Wk,
                                 const float* __restrict__ Wv,
                                 const float* __restrict__ Wo,
                                 __nv_bfloat16* __restrict__ wqkv,
                                 __nv_bfloat16* __restrict__ wo) {
    int l = blockIdx.z >> 2, m = blockIdx.z & 3;
    const float* W = (m == 0 ? Wq : m == 1 ? Wk : m == 2 ? Wv : Wo) + (size_t)l * DD * DD;
    __nv_bfloat16* dst = (m < 3)
        ? wqkv + (size_t)l * NQKV * K3D + (size_t)(m * DD) * K3D
        : wo   + (size_t)l * DD * K3D;
    packT_tile(W, dst, DD, DD, blockIdx.x * 32, blockIdx.y * 32,
               threadIdx.x, threadIdx.y);
}

__global__ void pack_w_kernel(const float* __restrict__ Wall,
                              __nv_bfloat16* __restrict__ dstAll,
                              int K, int N) {
    int l = blockIdx.z;
    packT_tile(Wall + (size_t)l * K * N, dstAll + (size_t)l * N * (3 * (size_t)K),
               K, N, blockIdx.x * 32, blockIdx.y * 32, threadIdx.x, threadIdx.y);
}

__global__ void pack_bias_kernel(const float* __restrict__ bq,
                                 const float* __restrict__ bk,
                                 const float* __restrict__ bv) {
    int l = blockIdx.y;
    int i = blockIdx.x * 256 + threadIdx.x;
    if (i < DD) {
        g_bqkv[l * NQKV + i]          = bq[l * DD + i];
        g_bqkv[l * NQKV + DD + i]     = bk[l * DD + i];
        g_bqkv[l * NQKV + 2 * DD + i] = bv[l * DD + i];
    }
}

// ---------------- embedding + pos emb (+ packed h3) -------------------------
__global__ void embed_kernel(const int* __restrict__ word_ids,
                             const float* __restrict__ word_emb) {
    int row = blockIdx.x;
    int l   = row % LL;
    int wid = word_ids[row];
    const float* we = word_emb + (size_t)wid * DD;
    float* out = g_h + (size_t)row * DD;
    __nv_bfloat16* p3 = g_h3 + (size_t)row * K3D;
#pragma unroll
    for (int t = 0; t < 3; t++) {
        int d  = threadIdx.x + t * 256;
        int m  = d >> 1;
        float div = __expf(-9.210340371976184f * (float)(2 * m) / (float)DD);
        float ang = (float)l * div;
        float pe  = (d & 1) ? cosf(ang) : sinf(ang);
        float v = we[d] + pe;
        out[d] = v;
        __nv_bfloat16 hi, lo; split_bf16(v, hi, lo);
        p3[d] = hi; p3[DD + d] = hi; p3[2*DD + d] = lo;
    }
}

// ---------------- WMMA bf16 GEMM, 3-stage cp.async, 64-K chunks -------------
// C[M,N] = A3[M,K3] @ Wt3[N,K3]^T + bias.  MODE 0: fp32 out; MODE 1: packed.
#define AST 72          /* smem stride (bf16): 144 B */
#define STG (128*AST)   /* per-tile per-stage elems */
#define CST 132
#define GEMM_SMEM (3*2*STG*2)   /* 110592 B >= Cs 128*132*4 = 67584 B */

template<bool RELU, int MODE>
__global__ __launch_bounds__(256)
void gemm_mma_kernel(const __nv_bfloat16* __restrict__ A,
                     const __nv_bfloat16* __restrict__ Bt,
                     const float* __restrict__ bias,
                     float* __restrict__ Cf,
                     __nv_bfloat16* __restrict__ Cp,
                     int K3, int N) {
    extern __shared__ char smraw[];
    __nv_bfloat16* As = (__nv_bfloat16*)smraw;          // [3][128][AST]
    __nv_bfloat16* Bs = As + 3 * STG;                   // [3][128][AST]
    float* Cs = (float*)smraw;                          // alias (epilogue)

    int tid = threadIdx.x;
    int wid = tid >> 5;
    int warpM = wid & 1;      // 64-row slab
    int warpN = wid >> 1;     // 32-col slab
    int rowBase = blockIdx.y * 128;
    int colBase = blockIdx.x * 128;

    const __nv_bfloat16* Ag = A  + (size_t)rowBase * K3;
    const __nv_bfloat16* Bg = Bt + (size_t)colBase * K3;
    uint32_t asB = smem_u32(As);
    uint32_t bsB = smem_u32(Bs);

    int r0  = tid >> 2;         // 0..63 base row
    int sgi = tid & 3;          // segment group
    int NK  = K3 >> 6;          // 64-K chunks

    auto load_stage = [&](int st, int kb) {
        uint32_t sOff = (uint32_t)st * (STG * 2);
        size_t gk = (size_t)kb * 64 + sgi * 8;
#pragma unroll
        for (int half = 0; half < 2; half++) {
            int row = r0 + half * 64;
#pragma unroll
            for (int t = 0; t < 2; t++) {
                size_t gcol = gk + t * 32;
                uint32_t so = sOff + (uint32_t)row * (AST * 2) + (sgi + t * 4) * 16;
                CP_ASYNC16(asB + so, Ag + (size_t)row * K3 + gcol);
                CP_ASYNC16(bsB + so, Bg + (size_t)row * K3 + gcol);
            }
        }
    };

    wmma::fragment<wmma::accumulator, 16,16,16, float> acc[4][2];
#pragma unroll
    for (int i = 0; i < 4; i++)
#pragma unroll
        for (int j = 0; j < 2; j++) wmma::fill_fragment(acc[i][j], 0.f);

    load_stage(0, 0); CP_COMMIT();
    load_stage(1, 1); CP_COMMIT();

    for (int i = 0; i < NK; i++) {
        CP_WAIT1();
        __syncthreads();
        if (i + 2 < NK) load_stage((i + 2) % 3, i + 2);
        CP_COMMIT();
        int st = i % 3;
        const __nv_bfloat16* Ast = As + st * STG;
        const __nv_bfloat16* Bst = Bs + st * STG;
#pragma unroll
        for (int ks = 0; ks < 64; ks += 16) {
            wmma::fragment<wmma::matrix_a, 16,16,16, __nv_bfloat16, wmma::row_major> af[4];
            wmma::fragment<wmma::matrix_b, 16,16,16, __nv_bfloat16, wmma::col_major> bf[2];
#pragma unroll
            for (int m4 = 0; m4 < 4; m4++)
                wmma::load_matrix_sync(af[m4], &Ast[(warpM*64 + m4*16)*AST + ks], AST);
#pragma unroll
            for (int n2 = 0; n2 < 2; n2++)
                wmma::load_matrix_sync(bf[n2], &Bst[(warpN*32 + n2*16)*AST + ks], AST);
#pragma unroll
            for (int m4 = 0; m4 < 4; m4++)
#pragma unroll
                for (int n2 = 0; n2 < 2; n2++)
                    wmma::mma_sync(acc[m4][n2], af[m4], bf[n2], acc[m4][n2]);
        }
    }
    CP_WAIT0();
    __syncthreads();

    // ---- epilogue: frags -> smem stage -> fused bias/relu -> gmem ----
#pragma unroll
    for (int m4 = 0; m4 < 4; m4++)
#pragma unroll
        for (int n2 = 0; n2 < 2; n2++)
            wmma::store_matrix_sync(&Cs[(warpM*64 + m4*16)*CST + warpN*32 + n2*16],
                                    acc[m4][n2], CST, wmma::mem_row_major);
    __syncthreads();

    int r  = tid >> 1;
    int c0 = (tid & 1) * 64;
    if (MODE == 0) {
#pragma unroll
        for (int c4 = 0; c4 < 64; c4 += 4) {
            int c = c0 + c4;
            float4 v = *(float4*)&Cs[r*CST + c];
            v.x += bias[colBase + c + 0];
            v.y += bias[colBase + c + 1];
            v.z += bias[colBase + c + 2];
            v.w += bias[colBase + c + 3];
            if (RELU) {
                v.x = fmaxf(v.x, 0.f); v.y = fmaxf(v.y, 0.f);
                v.z = fmaxf(v.z, 0.f); v.w = fmaxf(v.w, 0.f);
            }
            *(float4*)&Cf[(size_t)(rowBase + r) * N + colBase + c] = v;
        }
    } else {
        size_t rowb = (size_t)(rowBase + r) * (3 * (size_t)N);
#pragma unroll
        for (int c2 = 0; c2 < 64; c2 += 2) {
            int c = c0 + c2;
            float v0 = Cs[r*CST + c]     + bias[colBase + c];
            float v1 = Cs[r*CST + c + 1] + bias[colBase + c + 1];
            if (RELU) { v0 = fmaxf(v0, 0.f); v1 = fmaxf(v1, 0.f); }
            __nv_bfloat16 h0, l0, h1, l1;
            split_bf16(v0, h0, l0); split_bf16(v1, h1, l1);
            __nv_bfloat162 hh; hh.x = h0; hh.y = h1;
            __nv_bfloat162 llv; llv.x = l0; llv.y = l1;
            *(__nv_bfloat162*)&Cp[rowb + colBase + c]               = hh;
            *(__nv_bfloat162*)&Cp[rowb + N + colBase + c]           = hh;
            *(__nv_bfloat162*)&Cp[rowb + 2*(size_t)N + colBase + c] = llv;
        }
    }
}

// ---------------- fused attention (strided q/k/v; packed bf16 output) -------
#define ISPLIT 2
#define IBLK 4
#define KST 68
#define EST 68
#define ATT_SMEM_FLOATS (256*KST*2 + EE*EST + 256 + IBLK*52 + IBLK*256 + 32 + 8 + 256)

__global__ __launch_bounds__(256)
void attn_fused_kernel(const float* __restrict__ q,
                       const float* __restrict__ k,
                       const float* __restrict__ v,
                       int qstr,
                       const float* __restrict__ edge_emb,
                       const int* __restrict__ edge_types,
                       const int* __restrict__ adj,
                       __nv_bfloat16* __restrict__ outp3) {
    extern __shared__ float sm[];
    float* Ks  = sm;
    float* Vs  = Ks + 256 * KST;
    float* Et  = Vs + 256 * KST;
    float* qv  = Et + EE * EST;
    float* qe  = qv + IBLK * 64;
    float* pb  = qe + IBLK * 52;
    float* red = pb + IBLK * 256;
    float* mxs = red + 32;
    float* avs = mxs + 8;

    int h = blockIdx.x, b = blockIdx.y;
    int tid  = threadIdx.x;
    int lane = tid & 31, wrp = tid >> 5;

    const float* kbase = k + (size_t)(b * LL) * qstr + h * HDIM;
    const float* vbase = v + (size_t)(b * LL) * qstr + h * HDIM;
#pragma unroll
    for (int t = 0; t < 16; t++) {
        int idx = tid + t * 256;
        int j = idx >> 4, d4 = (idx & 15) * 4;
        float4 kv = *(const float4*)(kbase + (size_t)j * qstr + d4);
        float4 vv = *(const float4*)(vbase + (size_t)j * qstr + d4);
        Ks[j*KST + d4+0] = kv.x; Ks[j*KST + d4+1] = kv.y;
        Ks[j*KST + d4+2] = kv.z; Ks[j*KST + d4+3] = kv.w;
        Vs[j*KST + d4+0] = vv.x; Vs[j*KST + d4+1] = vv.y;
        Vs[j*KST + d4+2] = vv.z; Vs[j*KST + d4+3] = vv.w;
    }
    for (int idx = tid; idx < EE * 16; idx += 256) {
        int e = idx >> 4, d4 = (idx & 15) * 4;
        float4 ev = *(const float4*)(edge_emb + e * HDIM + d4);
        Et[e*EST + d4+0] = ev.x; Et[e*EST + d4+1] = ev.y;
        Et[e*EST + d4+2] = ev.z; Et[e*EST + d4+3] = ev.w;
    }
    __syncthreads();

    int i0 = blockIdx.z * (LL / ISPLIT);
    for (int qd = 0; qd < (LL / ISPLIT) / IBLK; qd++) {
        int ibase = i0 + qd * IBLK;
        {
            int iq = tid >> 6, d = tid & 63;
            qv[iq * 64 + d] = q[(size_t)(b * LL + ibase + iq) * qstr + h * HDIM + d];
        }
        __syncthreads();

        if (tid < IBLK * EE) {
            int iq = tid / EE, e = tid % EE;
            float s = 0.f;
            const float* qr = qv + iq * 64;
            const float* er = Et + e * EST;
#pragma unroll 8
            for (int d = 0; d < 64; d++) s += qr[d] * er[d];
            qe[iq * 52 + e] = s;
        }
        __syncthreads();

        int j = tid;
        float sarr[IBLK] = {};
        {
            const float4* Kr = (const float4*)(Ks + j * KST);
            const float4* Q0 = (const float4*)(qv);
            const float4* Q1 = (const float4*)(qv + 64);
            const float4* Q2 = (const float4*)(qv + 128);
            const float4* Q3 = (const float4*)(qv + 192);
#pragma unroll
            for (int d4 = 0; d4 < 16; d4++) {
                float4 kv = Kr[d4];
                float4 a;
                a = Q0[d4]; sarr[0] += a.x*kv.x + a.y*kv.y + a.z*kv.z + a.w*kv.w;
                a = Q1[d4]; sarr[1] += a.x*kv.x + a.y*kv.y + a.z*kv.z + a.w*kv.w;
                a = Q2[d4]; sarr[2] += a.x*kv.x + a.y*kv.y + a.z*kv.z + a.w*kv.w;
                a = Q3[d4]; sarr[3] += a.x*kv.x + a.y*kv.y + a.z*kv.z + a.w*kv.w;
            }
        }
#pragma unroll
        for (int iq = 0; iq < IBLK; iq++) {
            size_t eidx = (size_t)(b * LL + ibase + iq) * LL + j;
            int et = edge_types[eidx];
            sarr[iq] = (adj[eidx] != 0)
                     ? (sarr[iq] + qe[iq * 52 + et]) * 0.125f
                     : -1e9f;
        }
#pragma unroll
        for (int iq = 0; iq < IBLK; iq++) {
            float m = sarr[iq];
#pragma unroll
            for (int o = 16; o > 0; o >>= 1)
                m = fmaxf(m, __shfl_xor_sync(0xffffffffu, m, o));
            if (lane == 0) red[iq * 8 + wrp] = m;
        }
        __syncthreads();
        if (tid < IBLK) {
            float m = red[tid * 8];
#pragma unroll
            for (int w = 1; w < 8; w++) m = fmaxf(m, red[tid * 8 + w]);
            mxs[tid] = m;
        }
        __syncthreads();
        float ev[IBLK];
#pragma unroll
        for (int iq = 0; iq < IBLK; iq++) {
            ev[iq] = __expf(sarr[iq] - mxs[iq]);
            pb[iq * 256 + j] = ev[iq];
        }
#pragma unroll
        for (int iq = 0; iq < IBLK; iq++) {
            float s = ev[iq];
#pragma unroll
            for (int o = 16; o > 0; o >>= 1)
                s += __shfl_xor_sync(0xffffffffu, s, o);
            if (lane == 0) red[iq * 8 + wrp] = s;
        }
        __syncthreads();
        if (tid < IBLK) {
            float s = 0.f;
#pragma unroll
            for (int w = 0; w < 8; w++) s += red[tid * 8 + w];
            mxs[IBLK + tid] = 1.f / s;
        }
        __syncthreads();

        int d = tid & 63, part = tid >> 6;
#pragma unroll
        for (int iq = 0; iq < IBLK; iq++) {
            float acc = 0.f;
            const float4* pr = (const float4*)(pb + iq * 256 + part * 64);
            const float* vr = Vs + (size_t)(part * 64) * KST + d;
#pragma unroll 4
            for (int j4 = 0; j4 < 16; j4++) {
                float4 p4 = pr[j4];
                acc += p4.x * vr[(j4*4+0)*KST];
                acc += p4.y * vr[(j4*4+1)*KST];
                acc += p4.z * vr[(j4*4+2)*KST];
                acc += p4.w * vr[(j4*4+3)*KST];
            }
            avs[tid] = acc;
            __syncthreads();
            if (part == 0) {
                float o = (avs[d] + avs[64+d] + avs[128+d] + avs[192+d])
                          * mxs[IBLK + iq];
                size_t base = (size_t)(b * LL + ibase + iq) * K3D + h * HDIM + d;
                __nv_bfloat16 hi, lo; split_bf16(o, hi, lo);
                outp3[base] = hi; outp3[base + DD] = hi; outp3[base + 2*DD] = lo;
            }
            __syncthreads();
        }
    }
}

// ---------------- h = LayerNorm(h + proj); writes h + packed h3 -------------
__global__ void resln_kernel(const float* __restrict__ proj,
                             const float* __restrict__ gam,
                             const float* __restrict__ bet) {
    int row = blockIdx.x;
    int tid = threadIdx.x;
    __shared__ float rsum[256], rsq[256];
    float x[3];
    float s = 0.f, ss = 0.f;
#pragma unroll
    for (int t = 0; t < 3; t++) {
        int d = tid + t * 256;
        float v = g_h[(size_t)row * DD + d] + proj[(size_t)row * DD + d];
        x[t] = v; s += v; ss += v * v;
    }
    rsum[tid] = s; rsq[tid] = ss; __syncthreads();
    for (int st = 128; st > 0; st >>= 1) {
        if (tid < st) { rsum[tid] += rsum[tid + st]; rsq[tid] += rsq[tid + st]; }
        __syncthreads();
    }
    float mean = rsum[0] * (1.f / 768.f);
    float var  = rsq[0] * (1.f / 768.f) - mean * mean;
    float inv  = rsqrtf(var + 1e-5f);
    __nv_bfloat16* p3 = g_h3 + (size_t)row * K3D;
#pragma unroll
    for (int t = 0; t < 3; t++) {
        int d = tid + t * 256;
        float y = (x[t] - mean) * inv * gam[d] + bet[d];
        g_h[(size_t)row * DD + d] = y;
        __nv_bfloat16 hi, lo; split_bf16(y, hi, lo);
        p3[d] = hi; p3[DD + d] = hi; p3[2*DD + d] = lo;
    }
}

// ---------------- logits ----------------------------------------------------
__global__ void classify_kernel(const float* __restrict__ clsW,
                                const float* __restrict__ clsb,
                                float* __restrict__ out) {
    int b = blockIdx.x, c = blockIdx.y;
    int tid = threadIdx.x;
    __shared__ float red[256];
    const float* hrow = &g_h[(size_t)(b * LL) * DD];
    float s = 0.f;
    for (int d = tid; d < DD; d += 256) s += hrow[d] * clsW[d * CC + c];
    red[tid] = s; __syncthreads();
    for (int st = 128; st > 0; st >>= 1) {
        if (tid < st) red[tid] += red[tid + st];
        __syncthreads();
    }
    if (tid == 0) out[b * CC + c] = red[0] + clsb[c];
}

// ---------------- driver ----------------------------------------------------
extern "C" void kernel_launch(void* const* d_in, const int* in_sizes, int n_in,
                              void* d_out, int out_size) {
    const int*   word_ids   = (const int*)d_in[0];
    const int*   adj        = (const int*)d_in[1];
    const int*   edge_types = (const int*)d_in[2];
    const float* word_emb   = (const float*)d_in[3];
    const float* edge_emb   = (const float*)d_in[4];
    const float* Wq  = (const float*)d_in[5];
    const float* bq  = (const float*)d_in[6];
    const float* Wk  = (const float*)d_in[7];
    const float* bk  = (const float*)d_in[8];
    const float* Wv  = (const float*)d_in[9];
    const float* bv  = (const float*)d_in[10];
    const float* Wo  = (const float*)d_in[11];
    const float* bo  = (const float*)d_in[12];
    const float* ln1g = (const float*)d_in[13];
    const float* ln1b = (const float*)d_in[14];
    const float* W1  = (const float*)d_in[15];
    const float* b1  = (const float*)d_in[16];
    const float* W2  = (const float*)d_in[17];
    const float* b2  = (const float*)d_in[18];
    const float* ln2g = (const float*)d_in[19];
    const float* ln2b = (const float*)d_in[20];
    const float* clsW = (const float*)d_in[21];
    const float* clsb = (const float*)d_in[22];
    float* out = (float*)d_out;

    float *qkvptr, *pptr, *bqkvptr;
    __nv_bfloat16 *h3ptr, *ao3ptr, *ff3ptr, *wqkvptr, *woptr, *w1pptr, *w2pptr;
    cudaGetSymbolAddress((void**)&qkvptr, g_qkv);
    cudaGetSymbolAddress((void**)&pptr,   g_proj);
    cudaGetSymbolAddress((void**)&bqkvptr, g_bqkv);
    cudaGetSymbolAddress((void**)&h3ptr,  g_h3);
    cudaGetSymbolAddress((void**)&ao3ptr, g_ao3);
    cudaGetSymbolAddress((void**)&ff3ptr, g_ff3);
    cudaGetSymbolAddress((void**)&wqkvptr, g_wqkv);
    cudaGetSymbolAddress((void**)&woptr,   g_wo);
    cudaGetSymbolAddress((void**)&w1pptr,  g_w1p);
    cudaGetSymbolAddress((void**)&w2pptr,  g_w2p);

    cudaFuncSetAttribute(gemm_mma_kernel<false,0>,
                         cudaFuncAttributeMaxDynamicSharedMemorySize, GEMM_SMEM);
    cudaFuncSetAttribute(gemm_mma_kernel<true,1>,
                         cudaFuncAttributeMaxDynamicSharedMemorySize, GEMM_SMEM);
    const int attSmem = ATT_SMEM_FLOATS * 4;
    cudaFuncSetAttribute(attn_fused_kernel,
                         cudaFuncAttributeMaxDynamicSharedMemorySize, attSmem);

    // ---- pack all weights (4 launches) ----
    dim3 tb(32, 8);
    pack_qkvo_kernel<<<dim3(DD/32, DD/32, 4*NLAYER), tb>>>(Wq, Wk, Wv, Wo, wqkvptr, woptr);
    pack_w_kernel<<<dim3(DD/32, FFD/32, NLAYER), tb>>>(W1, w1pptr, DD, FFD);
    pack_w_kernel<<<dim3(FFD/32, DD/32, NLAYER), tb>>>(W2, w2pptr, FFD, DD);
    pack_bias_kernel<<<dim3(3, NLAYER), 256>>>(bq, bk, bv);

    dim3 gQKV(NQKV / 128, MM / 128);   // (18, 32)
    dim3 gD(DD / 128, MM / 128);       // (6, 32)
    dim3 gF(FFD / 128, MM / 128);      // (24, 32)

    embed_kernel<<<MM, 256>>>(word_ids, word_emb);

    for (int l = 0; l < NLAYER; l++) {
        gemm_mma_kernel<false,0><<<gQKV, 256, GEMM_SMEM>>>(
            h3ptr, wqkvptr + (size_t)l*NQKV*K3D, bqkvptr + l*NQKV,
            qkvptr, nullptr, K3D, NQKV);

        attn_fused_kernel<<<dim3(HH, BB, ISPLIT), 256, attSmem>>>(
            qkvptr, qkvptr + DD, qkvptr + 2*DD, NQKV,
            edge_emb, edge_types, adj, ao3ptr);

        gemm_mma_kernel<false,0><<<gD, 256, GEMM_SMEM>>>(
            ao3ptr, woptr + (size_t)l*DD*K3D, bo + l*DD, pptr, nullptr, K3D, DD);
        resln_kernel<<<MM, 256>>>(pptr, ln1g + l*DD, ln1b + l*DD);

        gemm_mma_kernel<true,1><<<gF, 256, GEMM_SMEM>>>(
            h3ptr, w1pptr + (size_t)l*FFD*K3D, b1 + l*FFD, nullptr, ff3ptr, K3D, FFD);
        gemm_mma_kernel<false,0><<<gD, 256, GEMM_SMEM>>>(
            ff3ptr, w2pptr + (size_t)l*DD*K3F, b2 + l*DD, pptr, nullptr, K3F, DD);
        resln_kernel<<<MM, 256>>>(pptr, ln2g + l*DD, ln2b + l*DD);
    }

    classify_kernel<<<dim3(BB, CC), 256>>>(clsW, clsb, out);
}